// round 14
// baseline (speedup 1.0000x reference)
#include <cuda_runtime.h>
#include <cuda_fp16.h>
#include <math.h>

#define Bsz 16
#define L   512
#define NH  12
#define HD  64
#define D   768
#define D3  2304
#define NC  20
#define BL  (Bsz*L)      // 8192
#define BH  (Bsz*NH)     // 192
#define LL  (L*L)        // 262144
#define KH  320          // padded K for hidden branch (300 -> 320)

// ---------------- scratch (allocation-free) ----------------
// token branch
__device__ __half g_x[(size_t)BL*D];
__device__ __half g_wt16[(size_t)D3*D];
__device__ __half g_att16[(size_t)BH*LL];
__device__ __half g_qn[(size_t)BH*L*HD];
__device__ __half g_kn[(size_t)BH*L*HD];
__device__ __half g_vt[(size_t)BH*HD*L];      // V transposed [z][d][l]
__device__ __half g_out[(size_t)BL*D];
__device__ float  g_probs[(size_t)BL*NC];
__device__ float  g_col[BL];
// hidden branch (independent copies so both branches run concurrently)
__device__ __half g_wh16[(size_t)D3*KH];
__device__ __half g_wv16[(size_t)BL*KH];
__device__ __half g_att16_2[(size_t)BH*LL];
__device__ __half g_qn2[(size_t)BH*L*HD];
__device__ __half g_kn2[(size_t)BH*L*HD];
__device__ __half g_vt2[(size_t)BH*HD*L];
__device__ __half g_out2[(size_t)BL*D];
__device__ float  g_probs2[(size_t)BL*NC];
__device__ float  g_col2[BL];

__device__ __forceinline__ float lrelu(float x) { return x >= 0.f ? x : 0.01f * x; }

__device__ __forceinline__ void mma16(float c[4], const unsigned a[4], const unsigned b[2]) {
    asm volatile(
        "mma.sync.aligned.m16n8k16.row.col.f32.f16.f16.f32 "
        "{%0,%1,%2,%3},{%4,%5,%6,%7},{%8,%9},{%0,%1,%2,%3};"
        : "+f"(c[0]), "+f"(c[1]), "+f"(c[2]), "+f"(c[3])
        : "r"(a[0]), "r"(a[1]), "r"(a[2]), "r"(a[3]), "r"(b[0]), "r"(b[1]));
}
__device__ __forceinline__ unsigned lds_u32(const __half* p) { return *(const unsigned*)p; }
__device__ __forceinline__ void cpasync16(void* smem, const void* gmem) {
    unsigned s = (unsigned)__cvta_generic_to_shared(smem);
    asm volatile("cp.async.cg.shared.global [%0], [%1], 16;\n" :: "r"(s), "l"(gmem));
}
__device__ __forceinline__ void cpcommit() { asm volatile("cp.async.commit_group;\n"); }
__device__ __forceinline__ void cpwait1()  { asm volatile("cp.async.wait_group 1;\n"); }
__device__ __forceinline__ void cpwait2()  { asm volatile("cp.async.wait_group 2;\n"); }

// ---------------- 0. fp32 -> fp16 (optionally K-padded rows) ----------------
__global__ void convpad_k(const float* __restrict__ src, __half* __restrict__ dst,
                          int K, int KP) {
    long long row = blockIdx.x;
    for (int k4 = threadIdx.x * 4; k4 < KP; k4 += blockDim.x * 4) {
        float4 v = (k4 + 4 <= K) ? *(const float4*)(src + row * K + k4)
                                 : make_float4(k4 < K ? src[row * K + k4] : 0.f,
                                               k4 + 1 < K ? src[row * K + k4 + 1] : 0.f,
                                               k4 + 2 < K ? src[row * K + k4 + 2] : 0.f,
                                               k4 + 3 < K ? src[row * K + k4 + 3] : 0.f);
        *(__half2*)(dst + row * KP + k4)     = __floats2half2_rn(v.x, v.y);
        *(__half2*)(dst + row * KP + k4 + 2) = __floats2half2_rn(v.z, v.w);
    }
}

// ---------------- 1. embedding + leaky -> fp16 ----------------
__global__ void embed_leaky_k(const int* __restrict__ ids, const float* __restrict__ emb,
                              __half* __restrict__ x) {
    int bl = blockIdx.x;
    long long id = ids[bl];
    const float* src = emb + id * D;
    __half* dst = x + (long long)bl * D;
    for (int k4 = threadIdx.x * 4; k4 < D; k4 += blockDim.x * 4) {
        float4 v = *(const float4*)(src + k4);
        *(__half2*)(dst + k4)     = __floats2half2_rn(lrelu(v.x), lrelu(v.y));
        *(__half2*)(dst + k4 + 2) = __floats2half2_rn(lrelu(v.z), lrelu(v.w));
    }
}

// ---------------- 2. fused proj GEMM + QKV split + cosine-norm + V transpose ----------------
__global__ void __launch_bounds__(256)
projsplit_k(const __half* __restrict__ A, int lda,
            const __half* __restrict__ W, int ldb,
            const float* __restrict__ bias,
            __half* __restrict__ qn, __half* __restrict__ kn,
            __half* __restrict__ vt, float* __restrict__ col, int K) {
    constexpr int BM = 128, BN = 128, WM = 32, WN = 64, BK = 32, PAD = 8, STG = 3;
    constexpr int IM = 2, IN = 8;

    __shared__ __align__(16) __half As[STG][BM][BK + PAD];
    __shared__ __align__(16) __half Bs[STG][BN][BK + PAD];

    const int tid = threadIdx.x;
    const int wid = tid >> 5, lane = tid & 31;
    const int g = lane >> 2, tg = lane & 3;
    const int wm = (wid >> 1) * WM, wn = (wid & 1) * WN;

    const __half* Ab = A + (long long)blockIdx.y * BM * lda;
    const __half* Bb = W + (long long)blockIdx.x * BN * ldb;

    const int ktiles = K / BK;
    float acc[IM][IN][4] = {};

    auto issue = [&](int t, int s) {
        int k0 = t * BK;
#pragma unroll
        for (int c = 0; c < 2; c++) {
            int idx = tid + c * 256;
            int row = idx >> 2, cq = idx & 3;
            cpasync16(&As[s][row][cq * 8], Ab + (long long)row * lda + k0 + cq * 8);
        }
#pragma unroll
        for (int c = 0; c < 2; c++) {
            int idx = tid + c * 256;
            int row = idx >> 2, cq = idx & 3;
            cpasync16(&Bs[s][row][cq * 8], Bb + (long long)row * ldb + k0 + cq * 8);
        }
    };

    issue(0, 0); cpcommit();
    if (ktiles > 1) issue(1, 1);
    cpcommit();
    cpwait1();
    __syncthreads();

    int rs = 0;
    for (int t = 0; t < ktiles; t++) {
#pragma unroll
        for (int kk = 0; kk < BK; kk += 16) {
            unsigned a[IM][4], b[IN][2];
#pragma unroll
            for (int im = 0; im < IM; im++) {
                int r = wm + im * 16 + g;
                a[im][0] = lds_u32(&As[rs][r][kk + tg * 2]);
                a[im][1] = lds_u32(&As[rs][r + 8][kk + tg * 2]);
                a[im][2] = lds_u32(&As[rs][r][kk + tg * 2 + 8]);
                a[im][3] = lds_u32(&As[rs][r + 8][kk + tg * 2 + 8]);
            }
#pragma unroll
            for (int in_ = 0; in_ < IN; in_++) {
                int r = wn + in_ * 8 + g;
                b[in_][0] = lds_u32(&Bs[rs][r][kk + tg * 2]);
                b[in_][1] = lds_u32(&Bs[rs][r][kk + tg * 2 + 8]);
            }
#pragma unroll
            for (int im = 0; im < IM; im++)
#pragma unroll
                for (int in_ = 0; in_ < IN; in_++)
                    mma16(acc[im][in_], a[im], b[in_]);
        }
        if (t + 2 < ktiles) issue(t + 2, (rs + 2) % STG);
        cpcommit();
        cpwait1();
        __syncthreads();
        rs = (rs + 1) % STG;
    }

    const int sec  = blockIdx.x / 6;                       // 0=Q, 1=K, 2=V
    const int m0   = blockIdx.y * BM;
    const int b    = m0 / L;
    const int l0   = m0 % L;

    if (blockIdx.x == 12 && tid < 128) col[b * L + l0 + tid] = 0.f;

#pragma unroll
    for (int im = 0; im < IM; im++)
#pragma unroll
        for (int in_ = 0; in_ < IN; in_++) {
            int cc = blockIdx.x * BN + wn + in_ * 8 + tg * 2;
            float b0 = bias[cc], b1 = bias[cc + 1];
            acc[im][in_][0] = lrelu(acc[im][in_][0] + b0);
            acc[im][in_][1] = lrelu(acc[im][in_][1] + b1);
            acc[im][in_][2] = lrelu(acc[im][in_][2] + b0);
            acc[im][in_][3] = lrelu(acc[im][in_][3] + b1);
        }

    if (sec < 2) {
        const int hloc = (blockIdx.x % 6) * 2 + (wn >> 6);
        const long long z = (long long)b * NH + hloc;
        __half* dst = (sec == 0) ? qn : kn;
#pragma unroll
        for (int im = 0; im < IM; im++) {
            float ss0 = 0.f, ss1 = 0.f;
#pragma unroll
            for (int in_ = 0; in_ < IN; in_++) {
                ss0 += acc[im][in_][0] * acc[im][in_][0] + acc[im][in_][1] * acc[im][in_][1];
                ss1 += acc[im][in_][2] * acc[im][in_][2] + acc[im][in_][3] * acc[im][in_][3];
            }
            ss0 += __shfl_xor_sync(0xffffffffu, ss0, 1);
            ss0 += __shfl_xor_sync(0xffffffffu, ss0, 2);
            ss1 += __shfl_xor_sync(0xffffffffu, ss1, 1);
            ss1 += __shfl_xor_sync(0xffffffffu, ss1, 2);
            float r0 = 1.f / fmaxf(sqrtf(ss0), 1e-8f);
            float r1 = 1.f / fmaxf(sqrtf(ss1), 1e-8f);
            int lA = l0 + wm + im * 16 + g;
            int lB = lA + 8;
#pragma unroll
            for (int in_ = 0; in_ < IN; in_++) {
                int dcol = in_ * 8 + tg * 2;
                *(__half2*)&dst[(z * L + lA) * HD + dcol] =
                    __floats2half2_rn(acc[im][in_][0] * r0, acc[im][in_][1] * r0);
                *(__half2*)&dst[(z * L + lB) * HD + dcol] =
                    __floats2half2_rn(acc[im][in_][2] * r1, acc[im][in_][3] * r1);
            }
        }
    } else {
        __half (*sv)[136] = (__half(*)[136])Bs;
#pragma unroll
        for (int p = 0; p < 2; p++) {
            __syncthreads();
            if ((wn >> 6) == p) {
#pragma unroll
                for (int im = 0; im < IM; im++)
#pragma unroll
                    for (int in_ = 0; in_ < IN; in_++) {
                        int d = in_ * 8 + tg * 2;
                        int l = wm + im * 16 + g;
                        sv[d][l]         = __float2half_rn(acc[im][in_][0]);
                        sv[d + 1][l]     = __float2half_rn(acc[im][in_][1]);
                        sv[d][l + 8]     = __float2half_rn(acc[im][in_][2]);
                        sv[d + 1][l + 8] = __float2half_rn(acc[im][in_][3]);
                    }
            }
            __syncthreads();
            long long z = (long long)b * NH + (blockIdx.x % 6) * 2 + p;
#pragma unroll
            for (int c = 0; c < 4; c++) {
                int idx = tid + c * 256;
                int d = idx >> 4, lc = (idx & 15) * 8;
                *(uint4*)(vt + (z * HD + d) * L + l0 + lc) = *(uint4*)&sv[d][lc];
            }
        }
    }
}

// ---------------- 3. fused scores + LN(heads): 3 CTAs/SM, lean registers ----------------
#define ATTLN6_SMEM (4*64*72*2 + 4*32*72*2)   // 55296
__global__ void __launch_bounds__(256, 3)
attln6_k(const __half* __restrict__ kn, const __half* __restrict__ qn,
         __half* __restrict__ att, const float* __restrict__ gamma,
         const float* __restrict__ beta) {
    extern __shared__ __align__(16) char smraw[];
    __half (*kbuf)[64][72] = (__half(*)[64][72])smraw;
    __half (*qbuf)[32][72] = (__half(*)[32][72])(smraw + 4*64*72*2);
    __half (*tile)[40] = (__half(*)[40])smraw;   // aliases kbuf after compute

    const int tid = threadIdx.x;
    const int wid = tid >> 5, lane = tid & 31;
    const int g = lane >> 2, tg = lane & 3;
    const int wm = (wid >> 1) * 16, wn = (wid & 1) * 16;
    const int J0 = blockIdx.x * 32, I0 = blockIdx.y * 64, b = blockIdx.z;

    const __half* kb = kn + ((long long)b * NH * L + I0) * HD;
    const __half* qb = qn + ((long long)b * NH * L + J0) * HD;

    __half2 sc[NH][4];

#define ISSUE(h)                                                                  \
    {                                                                             \
        int s_ = (h) & 3;                                                         \
        long long hoff = (long long)(h) * L * HD;                                 \
        _Pragma("unroll")                                                         \
        for (int c = 0; c < 2; c++) {                                             \
            int idx = tid + c * 256;                                              \
            int r = idx >> 3, jc = idx & 7;                                       \
            cpasync16(&kbuf[s_][r][jc * 8], kb + hoff + (long long)r * HD + jc * 8); \
        }                                                                         \
        { int r = tid >> 3, jc = tid & 7;                                         \
          cpasync16(&qbuf[s_][r][jc * 8], qb + hoff + (long long)r * HD + jc * 8); } \
        cpcommit();                                                               \
    }

#define COMPUTE(h)                                                                \
    {                                                                             \
        int s_ = (h) & 3;                                                         \
        float acc[2][4] = {};                                                     \
        _Pragma("unroll")                                                         \
        for (int kk = 0; kk < 64; kk += 16) {                                     \
            unsigned a[4];                                                        \
            a[0] = lds_u32(&kbuf[s_][wm + g][kk + tg * 2]);                       \
            a[1] = lds_u32(&kbuf[s_][wm + g + 8][kk + tg * 2]);                   \
            a[2] = lds_u32(&kbuf[s_][wm + g][kk + tg * 2 + 8]);                   \
            a[3] = lds_u32(&kbuf[s_][wm + g + 8][kk + tg * 2 + 8]);               \
            _Pragma("unroll")                                                     \
            for (int in_ = 0; in_ < 2; in_++) {                                   \
                unsigned bb[2];                                                   \
                bb[0] = lds_u32(&qbuf[s_][wn + in_ * 8 + g][kk + tg * 2]);        \
                bb[1] = lds_u32(&qbuf[s_][wn + in_ * 8 + g][kk + tg * 2 + 8]);    \
                mma16(acc[in_], a, bb);                                           \
            }                                                                     \
        }                                                                         \
        sc[h][0] = __floats2half2_rn(acc[0][0], acc[0][1]);                       \
        sc[h][1] = __floats2half2_rn(acc[0][2], acc[0][3]);                       \
        sc[h][2] = __floats2half2_rn(acc[1][0], acc[1][1]);                       \
        sc[h][3] = __floats2half2_rn(acc[1][2], acc[1][3]);                       \
    }

    ISSUE(0); ISSUE(1); ISSUE(2); ISSUE(3);
    cpwait2();
    __syncthreads();

#pragma unroll
    for (int p = 0; p < 6; p++) {
        COMPUTE(2 * p);
        COMPUTE(2 * p + 1);
        __syncthreads();
        if (p + 2 < 6) {
            ISSUE(2 * p + 4);
            ISSUE(2 * p + 5);
        } else {
            cpcommit(); cpcommit();
        }
        cpwait2();
        __syncthreads();
    }
#undef ISSUE
#undef COMPUTE

    // LN across heads, streaming (reg-lean): overwrite sc with LN'd values
#pragma unroll
    for (int p = 0; p < 4; p++) {
        float mux = 0.f, muy = 0.f;
#pragma unroll
        for (int h = 0; h < NH; h++) {
            float2 f = __half22float2(sc[h][p]);
            mux += f.x; muy += f.y;
        }
        mux *= (1.f / NH); muy *= (1.f / NH);
        float varx = 0.f, vary = 0.f;
#pragma unroll
        for (int h = 0; h < NH; h++) {
            float2 f = __half22float2(sc[h][p]);
            float dx = f.x - mux, dy = f.y - muy;
            varx += dx * dx; vary += dy * dy;
        }
        float rsx = rsqrtf(varx * (1.f / NH) + 1e-5f);
        float rsy = rsqrtf(vary * (1.f / NH) + 1e-5f);
#pragma unroll
        for (int h = 0; h < NH; h++) {
            float2 f = __half22float2(sc[h][p]);
            float gmh = gamma[h], beh = beta[h];
            sc[h][p] = __floats2half2_rn((f.x - mux) * rsx * gmh + beh,
                                         (f.y - muy) * rsy * gmh + beh);
        }
    }

    // staged, coalesced output: per head stage 64x32 tile in smem, write 64B rows
    __half* ob = att + (long long)b * NH * LL + (long long)I0 * L + J0;
    const int trow = tid >> 2, tcol = (tid & 3) * 8;
#pragma unroll
    for (int h = 0; h < NH; h++) {
        __syncthreads();
#pragma unroll
        for (int p = 0; p < 4; p++) {
            int i = wm + g + ((p & 1) ? 8 : 0);
            int j = wn + ((p >> 1) ? 8 : 0) + tg * 2;
            *(__half2*)&tile[i][j] = sc[h][p];
        }
        __syncthreads();
        *(uint4*)&ob[(long long)h * LL + (long long)trow * L + tcol] =
            *(uint4*)&tile[trow][tcol];
    }
}

// ---------------- 4. fused softmax + colsum + att@V (fp16 out) ----------------
#define SMATTV_SMEM (64*520*2 + 2*64*72*2)   // 84992
__global__ void __launch_bounds__(256, 2)
smattv_k(const __half* __restrict__ att, const __half* __restrict__ vt,
         __half* __restrict__ out, float* __restrict__ col) {
    extern __shared__ __align__(16) char smem_raw[];
    __half (*satt)[520] = (__half(*)[520])smem_raw;
    __half (*vbuf)[64][72] = (__half(*)[64][72])(smem_raw + 64*520*2);

    const int tid = threadIdx.x;
    const int wid = tid >> 5, lane = tid & 31;
    const int g = lane >> 2, tg = lane & 3;
    const int wm = (wid >> 1) * 16, wn = (wid & 1) * 32;
    const int I0 = blockIdx.x * 64;
    const int z = blockIdx.y;
    const int b = z / NH, h = z % NH;

    const __half* abase = att + (long long)z * LL + (long long)I0 * L;
    const __half* vbase = vt + (long long)z * HD * L;

#pragma unroll
    for (int c = 0; c < 16; c++) {
        int idx = tid + c * 256;
        int r = idx >> 6, jc = idx & 63;
        cpasync16(&satt[r][jc * 8], abase + (long long)r * L + jc * 8);
    }
    cpcommit();

#define ISSUEV(kt, s)                                                            \
    {                                                                            \
        _Pragma("unroll")                                                        \
        for (int c = 0; c < 2; c++) {                                            \
            int idx = tid + c * 256;                                             \
            int r = idx >> 3, jc = idx & 7;                                      \
            cpasync16(&vbuf[s][r][jc * 8], vbase + (long long)r * L + (kt) * 64 + jc * 8); \
        }                                                                        \
    }
    ISSUEV(0, 0); cpcommit();
    cpwait1();
    __syncthreads();

    for (int k = 0; k < 8; k++) {
        int r = wid * 8 + k;
        float v[16];
        float m = -1e30f;
#pragma unroll
        for (int q = 0; q < 8; q++) {
            float2 f = __half22float2(*(__half2*)&satt[r][lane * 2 + q * 64]);
            v[2 * q] = f.x; v[2 * q + 1] = f.y;
            m = fmaxf(m, fmaxf(f.x, f.y));
        }
#pragma unroll
        for (int o = 16; o; o >>= 1) m = fmaxf(m, __shfl_xor_sync(0xffffffffu, m, o));
        float s = 0.f;
#pragma unroll
        for (int q = 0; q < 16; q++) { v[q] = __expf(v[q] - m); s += v[q]; }
#pragma unroll
        for (int o = 16; o; o >>= 1) s += __shfl_xor_sync(0xffffffffu, s, o);
        float inv = 1.f / s;
#pragma unroll
        for (int q = 0; q < 8; q++)
            *(__half2*)&satt[r][lane * 2 + q * 64] =
                __floats2half2_rn(v[2 * q] * inv, v[2 * q + 1] * inv);
    }
    __syncthreads();

    {
        int j = tid * 2;
        float c0 = 0.f, c1 = 0.f;
#pragma unroll 8
        for (int r = 0; r < 64; r++) {
            float2 f = __half22float2(*(__half2*)&satt[r][j]);
            c0 += f.x; c1 += f.y;
        }
        atomicAdd(&col[b * L + j], c0 * (1.f / NH));
        atomicAdd(&col[b * L + j + 1], c1 * (1.f / NH));
    }

    float acc[4][4] = {};
    int rs = 0;
    for (int kt = 0; kt < 8; kt++) {
        if (kt + 1 < 8) ISSUEV(kt + 1, rs ^ 1);
        cpcommit();
        cpwait1();
        __syncthreads();
#pragma unroll
        for (int kk = 0; kk < 64; kk += 16) {
            unsigned a[4];
            int kc = kt * 64 + kk + tg * 2;
            a[0] = lds_u32(&satt[wm + g][kc]);
            a[1] = lds_u32(&satt[wm + g + 8][kc]);
            a[2] = lds_u32(&satt[wm + g][kc + 8]);
            a[3] = lds_u32(&satt[wm + g + 8][kc + 8]);
#pragma unroll
            for (int in_ = 0; in_ < 4; in_++) {
                unsigned bb[2];
                bb[0] = lds_u32(&vbuf[rs][wn + in_ * 8 + g][kk + tg * 2]);
                bb[1] = lds_u32(&vbuf[rs][wn + in_ * 8 + g][kk + tg * 2 + 8]);
                mma16(acc[in_], a, bb);
            }
        }
        rs ^= 1;
        __syncthreads();
    }
#undef ISSUEV

    __half* ob = out + ((long long)b * L + I0) * D + h * HD;
#pragma unroll
    for (int in_ = 0; in_ < 4; in_++) {
        int c = wn + in_ * 8 + tg * 2;
        *(__half2*)&ob[(long long)(wm + g) * D + c] =
            __floats2half2_rn(acc[in_][0], acc[in_][1]);
        *(__half2*)&ob[(long long)(wm + g + 8) * D + c] =
            __floats2half2_rn(acc[in_][2], acc[in_][3]);
    }
}

// ---------------- 5. per-token class probs (fp16 input) ----------------
__global__ void probs_k(const __half* __restrict__ out, const float* __restrict__ Wout,
                        const float* __restrict__ bout, float* __restrict__ probs) {
    int bl = blockIdx.x;
    int warp = threadIdx.x >> 5, lane = threadIdx.x & 31;
    __shared__ float s[NC];
    __shared__ float mx, sum;
    const __half* row = out + (long long)bl * D;
#pragma unroll
    for (int cc = 0; cc < 4; cc++) {
        int c = warp * 4 + cc;
        const float* w = Wout + c * D;
        float acc = 0.f;
        for (int k = lane * 2; k < D; k += 64) {
            float2 f = __half22float2(*(const __half2*)(row + k));
            acc += f.x * w[k] + f.y * w[k + 1];
        }
#pragma unroll
        for (int o = 16; o; o >>= 1) acc += __shfl_down_sync(0xffffffffu, acc, o);
        if (lane == 0) s[c] = acc + bout[c];
    }
    __syncthreads();
    if (threadIdx.x == 0) {
        float m = -1e30f;
        for (int c = 0; c < NC; c++) m = fmaxf(m, s[c]);
        float ss = 0.f;
        for (int c = 0; c < NC; c++) ss += __expf(s[c] - m);
        mx = m; sum = ss;
    }
    __syncthreads();
    if (threadIdx.x < NC)
        probs[(long long)bl * NC + threadIdx.x] = __expf(s[threadIdx.x] - mx) / sum;
}

// ---------------- 6. fused token weights softmax + final reduce ----------------
__global__ void __launch_bounds__(512)
wfinal_k(const int* __restrict__ ids, const float* __restrict__ col,
         const float* __restrict__ probs, float* __restrict__ dout, int first) {
    int b = blockIdx.x, l = threadIdx.x;
    int wid = l >> 5, lane = l & 31;
    __shared__ float red[512];
    __shared__ float psum[16][NC];

    float w = (ids[b * L + l] != 0 ? 1.f : 0.f) * col[b * L + l];
    red[l] = w;
    __syncthreads();
    for (int o = 256; o; o >>= 1) { if (l < o) red[l] = fmaxf(red[l], red[l + o]); __syncthreads(); }
    float mxv = red[0];
    __syncthreads();
    float e = __expf(w - mxv);
    red[l] = e;
    __syncthreads();
    for (int o = 256; o; o >>= 1) { if (l < o) red[l] += red[l + o]; __syncthreads(); }
    float wg = e / red[0];

    const float* pb = probs + (long long)(b * L + l) * NC;
    float myp[NC];
#pragma unroll
    for (int c = 0; c < NC; c++) myp[c] = wg * pb[c];
#pragma unroll
    for (int c = 0; c < NC; c++) {
        float v = myp[c];
#pragma unroll
        for (int o = 16; o; o >>= 1) v += __shfl_xor_sync(0xffffffffu, v, o);
        if (lane == 0) psum[wid][c] = v;
    }
    __syncthreads();
    if (l < NC) {
        float s = 0.f;
#pragma unroll
        for (int q = 0; q < 16; q++) s += psum[q][l];
        float v = 0.5f * s;
        dout[b * NC + l] = first ? v : dout[b * NC + l] + v;
    }
}

// ---------------- launch ----------------
extern "C" void kernel_launch(void* const* d_in, const int* in_sizes, int n_in,
                              void* d_out, int out_size) {
    (void)in_sizes; (void)n_in; (void)out_size;
    const int*   ids   = (const int*)d_in[0];
    const float* wv    = (const float*)d_in[1];
    const float* emb   = (const float*)d_in[2];
    const float* W_t   = (const float*)d_in[3];
    const float* b_t   = (const float*)d_in[4];
    const float* gam_t = (const float*)d_in[5];
    const float* bet_t = (const float*)d_in[6];
    const float* Wo_t  = (const float*)d_in[7];
    const float* bo_t  = (const float*)d_in[8];
    const float* W_h   = (const float*)d_in[9];
    const float* b_h   = (const float*)d_in[10];
    const float* gam_h = (const float*)d_in[11];
    const float* bet_h = (const float*)d_in[12];
    const float* Wo_h  = (const float*)d_in[13];
    const float* bo_h  = (const float*)d_in[14];
    float* out = (float*)d_out;

    __half *px, *pwt, *pwh, *pwv, *patt16, *pqn, *pkn, *pvt, *pout;
    __half *patt16_2, *pqn2, *pkn2, *pvt2, *pout2;
    float *pprobs, *pcol, *pprobs2, *pcol2;
    cudaGetSymbolAddress((void**)&px, g_x);
    cudaGetSymbolAddress((void**)&pwt, g_wt16);
    cudaGetSymbolAddress((void**)&pwh, g_wh16);
    cudaGetSymbolAddress((void**)&pwv, g_wv16);
    cudaGetSymbolAddress((void**)&patt16, g_att16);
    cudaGetSymbolAddress((void**)&pqn, g_qn);
    cudaGetSymbolAddress((void**)&pkn, g_kn);
    cudaGetSymbolAddress((void**)&pvt, g_vt);
    cudaGetSymbolAddress((void**)&pout, g_out);
    cudaGetSymbolAddress((void**)&pprobs, g_probs);
    cudaGetSymbolAddress((void**)&pcol, g_col);
    cudaGetSymbolAddress((void**)&patt16_2, g_att16_2);
    cudaGetSymbolAddress((void**)&pqn2, g_qn2);
    cudaGetSymbolAddress((void**)&pkn2, g_kn2);
    cudaGetSymbolAddress((void**)&pvt2, g_vt2);
    cudaGetSymbolAddress((void**)&pout2, g_out2);
    cudaGetSymbolAddress((void**)&pprobs2, g_probs2);
    cudaGetSymbolAddress((void**)&pcol2, g_col2);

    cudaFuncSetAttribute(smattv_k, cudaFuncAttributeMaxDynamicSharedMemorySize, SMATTV_SMEM);
    cudaFuncSetAttribute(attln6_k, cudaFuncAttributeMaxDynamicSharedMemorySize, ATTLN6_SMEM);

    dim3 proj_grid(D3 / 128, BL / 128);
    dim3 attln_grid(L / 32, L / 64, Bsz);
    dim3 smattv_grid(L / 64, BH);

    // Fork a second stream for the independent hidden branch (graph-capturable;
    // created per call, intentionally not destroyed — see R7 notes).
    cudaStream_t s2;
    cudaStreamCreateWithFlags(&s2, cudaStreamNonBlocking);
    cudaEvent_t evFork, evJoin;
    cudaEventCreateWithFlags(&evFork, cudaEventDisableTiming);
    cudaEventCreateWithFlags(&evJoin, cudaEventDisableTiming);

    cudaEventRecord(evFork, 0);
    cudaStreamWaitEvent(s2, evFork, 0);

    // ===== token branch (main stream) =====
    embed_leaky_k<<<BL, 192>>>(ids, emb, px);
    convpad_k<<<D3, 192>>>(W_t, pwt, D, D);
    projsplit_k<<<proj_grid, 256>>>(px, D, pwt, D, b_t, pqn, pkn, pvt, pcol, D);
    attln6_k<<<attln_grid, 256, ATTLN6_SMEM>>>(pkn, pqn, patt16, gam_t, bet_t);
    smattv_k<<<smattv_grid, 256, SMATTV_SMEM>>>(patt16, pvt, pout, pcol);
    probs_k<<<BL, 160>>>(pout, Wo_t, bo_t, pprobs);
    wfinal_k<<<Bsz, 512>>>(ids, pcol, pprobs, out, 1);

    // ===== hidden / word-vector branch (stream s2) =====
    convpad_k<<<D3, 128, 0, s2>>>(W_h, pwh, 300, KH);
    convpad_k<<<BL, 128, 0, s2>>>(wv, pwv, 300, KH);
    projsplit_k<<<proj_grid, 256, 0, s2>>>(pwv, KH, pwh, KH, b_h, pqn2, pkn2, pvt2, pcol2, KH);
    attln6_k<<<attln_grid, 256, ATTLN6_SMEM, s2>>>(pkn2, pqn2, patt16_2, gam_h, bet_h);
    smattv_k<<<smattv_grid, 256, SMATTV_SMEM, s2>>>(patt16_2, pvt2, pout2, pcol2);
    probs_k<<<BL, 160, 0, s2>>>(pout2, Wo_h, bo_h, pprobs2);

    // join: hidden-branch results folded into d_out on the main stream
    cudaEventRecord(evJoin, s2);
    cudaStreamWaitEvent(0, evJoin, 0);
    wfinal_k<<<Bsz, 512>>>(ids, pcol2, pprobs2, out, 0);
}

// round 15
// speedup vs baseline: 1.0987x; 1.0987x over previous
#include <cuda_runtime.h>
#include <cuda_fp16.h>
#include <math.h>

#define Bsz 16
#define L   512
#define NH  12
#define HD  64
#define D   768
#define D3  2304
#define NC  20
#define BL  (Bsz*L)      // 8192
#define BH  (Bsz*NH)     // 192
#define LL  (L*L)        // 262144
#define KH  320          // padded K for hidden branch (300 -> 320)

// ---------------- scratch (allocation-free) ----------------
// token branch
__device__ __half g_x[(size_t)BL*D];
__device__ __half g_wt16[(size_t)D3*D];
__device__ __half g_wot16[(size_t)NC*D];
__device__ __half g_att16[(size_t)BH*LL];
__device__ __half g_qn[(size_t)BH*L*HD];
__device__ __half g_kn[(size_t)BH*L*HD];
__device__ __half g_vt[(size_t)BH*HD*L];      // V transposed [z][d][l]
__device__ __half g_out[(size_t)BL*D];
__device__ float  g_probs[(size_t)BL*NC];
__device__ float  g_col[BL];
// hidden branch (independent copies so both branches run concurrently)
__device__ __half g_wh16[(size_t)D3*KH];
__device__ __half g_wv16[(size_t)BL*KH];
__device__ __half g_woh16[(size_t)NC*D];
__device__ __half g_att16_2[(size_t)BH*LL];
__device__ __half g_qn2[(size_t)BH*L*HD];
__device__ __half g_kn2[(size_t)BH*L*HD];
__device__ __half g_vt2[(size_t)BH*HD*L];
__device__ __half g_out2[(size_t)BL*D];
__device__ float  g_probs2[(size_t)BL*NC];
__device__ float  g_col2[BL];

__device__ __forceinline__ float lrelu(float x) { return x >= 0.f ? x : 0.01f * x; }

__device__ __forceinline__ void mma16(float c[4], const unsigned a[4], const unsigned b[2]) {
    asm volatile(
        "mma.sync.aligned.m16n8k16.row.col.f32.f16.f16.f32 "
        "{%0,%1,%2,%3},{%4,%5,%6,%7},{%8,%9},{%0,%1,%2,%3};"
        : "+f"(c[0]), "+f"(c[1]), "+f"(c[2]), "+f"(c[3])
        : "r"(a[0]), "r"(a[1]), "r"(a[2]), "r"(a[3]), "r"(b[0]), "r"(b[1]));
}
__device__ __forceinline__ unsigned lds_u32(const __half* p) { return *(const unsigned*)p; }
__device__ __forceinline__ void cpasync16(void* smem, const void* gmem) {
    unsigned s = (unsigned)__cvta_generic_to_shared(smem);
    asm volatile("cp.async.cg.shared.global [%0], [%1], 16;\n" :: "r"(s), "l"(gmem));
}
__device__ __forceinline__ void cpcommit() { asm volatile("cp.async.commit_group;\n"); }
__device__ __forceinline__ void cpwait1()  { asm volatile("cp.async.wait_group 1;\n"); }
__device__ __forceinline__ void cpwait2()  { asm volatile("cp.async.wait_group 2;\n"); }

// ---------------- 0. fp32 -> fp16 (optionally K-padded rows) ----------------
__global__ void convpad_k(const float* __restrict__ src, __half* __restrict__ dst,
                          int K, int KP) {
    long long row = blockIdx.x;
    for (int k4 = threadIdx.x * 4; k4 < KP; k4 += blockDim.x * 4) {
        float4 v = (k4 + 4 <= K) ? *(const float4*)(src + row * K + k4)
                                 : make_float4(k4 < K ? src[row * K + k4] : 0.f,
                                               k4 + 1 < K ? src[row * K + k4 + 1] : 0.f,
                                               k4 + 2 < K ? src[row * K + k4 + 2] : 0.f,
                                               k4 + 3 < K ? src[row * K + k4 + 3] : 0.f);
        *(__half2*)(dst + row * KP + k4)     = __floats2half2_rn(v.x, v.y);
        *(__half2*)(dst + row * KP + k4 + 2) = __floats2half2_rn(v.z, v.w);
    }
}

// ---------------- 1. embedding + leaky -> fp16 ----------------
__global__ void embed_leaky_k(const int* __restrict__ ids, const float* __restrict__ emb,
                              __half* __restrict__ x) {
    int bl = blockIdx.x;
    long long id = ids[bl];
    const float* src = emb + id * D;
    __half* dst = x + (long long)bl * D;
    for (int k4 = threadIdx.x * 4; k4 < D; k4 += blockDim.x * 4) {
        float4 v = *(const float4*)(src + k4);
        *(__half2*)(dst + k4)     = __floats2half2_rn(lrelu(v.x), lrelu(v.y));
        *(__half2*)(dst + k4 + 2) = __floats2half2_rn(lrelu(v.z), lrelu(v.w));
    }
}

// ---------------- 2. fused proj GEMM + QKV split + cosine-norm + V transpose ----------------
__global__ void __launch_bounds__(256)
projsplit_k(const __half* __restrict__ A, int lda,
            const __half* __restrict__ W, int ldb,
            const float* __restrict__ bias,
            __half* __restrict__ qn, __half* __restrict__ kn,
            __half* __restrict__ vt, float* __restrict__ col, int K) {
    constexpr int BM = 128, BN = 128, WM = 32, WN = 64, BK = 32, PAD = 8, STG = 3;
    constexpr int IM = 2, IN = 8;

    __shared__ __align__(16) __half As[STG][BM][BK + PAD];
    __shared__ __align__(16) __half Bs[STG][BN][BK + PAD];

    const int tid = threadIdx.x;
    const int wid = tid >> 5, lane = tid & 31;
    const int g = lane >> 2, tg = lane & 3;
    const int wm = (wid >> 1) * WM, wn = (wid & 1) * WN;

    const __half* Ab = A + (long long)blockIdx.y * BM * lda;
    const __half* Bb = W + (long long)blockIdx.x * BN * ldb;

    const int ktiles = K / BK;
    float acc[IM][IN][4] = {};

    auto issue = [&](int t, int s) {
        int k0 = t * BK;
#pragma unroll
        for (int c = 0; c < 2; c++) {
            int idx = tid + c * 256;
            int row = idx >> 2, cq = idx & 3;
            cpasync16(&As[s][row][cq * 8], Ab + (long long)row * lda + k0 + cq * 8);
        }
#pragma unroll
        for (int c = 0; c < 2; c++) {
            int idx = tid + c * 256;
            int row = idx >> 2, cq = idx & 3;
            cpasync16(&Bs[s][row][cq * 8], Bb + (long long)row * ldb + k0 + cq * 8);
        }
    };

    issue(0, 0); cpcommit();
    if (ktiles > 1) issue(1, 1);
    cpcommit();
    cpwait1();
    __syncthreads();

    int rs = 0;
    for (int t = 0; t < ktiles; t++) {
#pragma unroll
        for (int kk = 0; kk < BK; kk += 16) {
            unsigned a[IM][4], b[IN][2];
#pragma unroll
            for (int im = 0; im < IM; im++) {
                int r = wm + im * 16 + g;
                a[im][0] = lds_u32(&As[rs][r][kk + tg * 2]);
                a[im][1] = lds_u32(&As[rs][r + 8][kk + tg * 2]);
                a[im][2] = lds_u32(&As[rs][r][kk + tg * 2 + 8]);
                a[im][3] = lds_u32(&As[rs][r + 8][kk + tg * 2 + 8]);
            }
#pragma unroll
            for (int in_ = 0; in_ < IN; in_++) {
                int r = wn + in_ * 8 + g;
                b[in_][0] = lds_u32(&Bs[rs][r][kk + tg * 2]);
                b[in_][1] = lds_u32(&Bs[rs][r][kk + tg * 2 + 8]);
            }
#pragma unroll
            for (int im = 0; im < IM; im++)
#pragma unroll
                for (int in_ = 0; in_ < IN; in_++)
                    mma16(acc[im][in_], a[im], b[in_]);
        }
        if (t + 2 < ktiles) issue(t + 2, (rs + 2) % STG);
        cpcommit();
        cpwait1();
        __syncthreads();
        rs = (rs + 1) % STG;
    }

    const int sec  = blockIdx.x / 6;                       // 0=Q, 1=K, 2=V
    const int m0   = blockIdx.y * BM;
    const int b    = m0 / L;
    const int l0   = m0 % L;

    if (blockIdx.x == 12 && tid < 128) col[b * L + l0 + tid] = 0.f;

#pragma unroll
    for (int im = 0; im < IM; im++)
#pragma unroll
        for (int in_ = 0; in_ < IN; in_++) {
            int cc = blockIdx.x * BN + wn + in_ * 8 + tg * 2;
            float b0 = bias[cc], b1 = bias[cc + 1];
            acc[im][in_][0] = lrelu(acc[im][in_][0] + b0);
            acc[im][in_][1] = lrelu(acc[im][in_][1] + b1);
            acc[im][in_][2] = lrelu(acc[im][in_][2] + b0);
            acc[im][in_][3] = lrelu(acc[im][in_][3] + b1);
        }

    if (sec < 2) {
        const int hloc = (blockIdx.x % 6) * 2 + (wn >> 6);
        const long long z = (long long)b * NH + hloc;
        __half* dst = (sec == 0) ? qn : kn;
#pragma unroll
        for (int im = 0; im < IM; im++) {
            float ss0 = 0.f, ss1 = 0.f;
#pragma unroll
            for (int in_ = 0; in_ < IN; in_++) {
                ss0 += acc[im][in_][0] * acc[im][in_][0] + acc[im][in_][1] * acc[im][in_][1];
                ss1 += acc[im][in_][2] * acc[im][in_][2] + acc[im][in_][3] * acc[im][in_][3];
            }
            ss0 += __shfl_xor_sync(0xffffffffu, ss0, 1);
            ss0 += __shfl_xor_sync(0xffffffffu, ss0, 2);
            ss1 += __shfl_xor_sync(0xffffffffu, ss1, 1);
            ss1 += __shfl_xor_sync(0xffffffffu, ss1, 2);
            float r0 = 1.f / fmaxf(sqrtf(ss0), 1e-8f);
            float r1 = 1.f / fmaxf(sqrtf(ss1), 1e-8f);
            int lA = l0 + wm + im * 16 + g;
            int lB = lA + 8;
#pragma unroll
            for (int in_ = 0; in_ < IN; in_++) {
                int dcol = in_ * 8 + tg * 2;
                *(__half2*)&dst[(z * L + lA) * HD + dcol] =
                    __floats2half2_rn(acc[im][in_][0] * r0, acc[im][in_][1] * r0);
                *(__half2*)&dst[(z * L + lB) * HD + dcol] =
                    __floats2half2_rn(acc[im][in_][2] * r1, acc[im][in_][3] * r1);
            }
        }
    } else {
        __half (*sv)[136] = (__half(*)[136])Bs;
#pragma unroll
        for (int p = 0; p < 2; p++) {
            __syncthreads();
            if ((wn >> 6) == p) {
#pragma unroll
                for (int im = 0; im < IM; im++)
#pragma unroll
                    for (int in_ = 0; in_ < IN; in_++) {
                        int d = in_ * 8 + tg * 2;
                        int l = wm + im * 16 + g;
                        sv[d][l]         = __float2half_rn(acc[im][in_][0]);
                        sv[d + 1][l]     = __float2half_rn(acc[im][in_][1]);
                        sv[d][l + 8]     = __float2half_rn(acc[im][in_][2]);
                        sv[d + 1][l + 8] = __float2half_rn(acc[im][in_][3]);
                    }
            }
            __syncthreads();
            long long z = (long long)b * NH + (blockIdx.x % 6) * 2 + p;
#pragma unroll
            for (int c = 0; c < 4; c++) {
                int idx = tid + c * 256;
                int d = idx >> 4, lc = (idx & 15) * 8;
                *(uint4*)(vt + (z * HD + d) * L + l0 + lc) = *(uint4*)&sv[d][lc];
            }
        }
    }
}

// ---------------- 3. fused scores + LN(heads): 2 heads/stage, coalesced writes ----------------
#define ATTLN5_SMEM (4*64*72*2 + 4*32*72*2)   // 55296
__global__ void __launch_bounds__(256, 2)
attln5_k(const __half* __restrict__ kn, const __half* __restrict__ qn,
         __half* __restrict__ att, const float* __restrict__ gamma,
         const float* __restrict__ beta) {
    extern __shared__ __align__(16) char smraw[];
    __half (*kbuf)[64][72] = (__half(*)[64][72])smraw;
    __half (*qbuf)[32][72] = (__half(*)[32][72])(smraw + 4*64*72*2);
    __half (*tile)[40] = (__half(*)[40])smraw;   // aliases kbuf after compute

    const int tid = threadIdx.x;
    const int wid = tid >> 5, lane = tid & 31;
    const int g = lane >> 2, tg = lane & 3;
    const int wm = (wid >> 1) * 16, wn = (wid & 1) * 16;
    const int J0 = blockIdx.x * 32, I0 = blockIdx.y * 64, b = blockIdx.z;

    const __half* kb = kn + ((long long)b * NH * L + I0) * HD;
    const __half* qb = qn + ((long long)b * NH * L + J0) * HD;

    __half2 sc[NH][4];

#define ISSUE(h)                                                                  \
    {                                                                             \
        int s_ = (h) & 3;                                                         \
        long long hoff = (long long)(h) * L * HD;                                 \
        _Pragma("unroll")                                                         \
        for (int c = 0; c < 2; c++) {                                             \
            int idx = tid + c * 256;                                              \
            int r = idx >> 3, jc = idx & 7;                                       \
            cpasync16(&kbuf[s_][r][jc * 8], kb + hoff + (long long)r * HD + jc * 8); \
        }                                                                         \
        { int r = tid >> 3, jc = tid & 7;                                         \
          cpasync16(&qbuf[s_][r][jc * 8], qb + hoff + (long long)r * HD + jc * 8); } \
        cpcommit();                                                               \
    }

#define COMPUTE(h)                                                                \
    {                                                                             \
        int s_ = (h) & 3;                                                         \
        float acc[2][4] = {};                                                     \
        _Pragma("unroll")                                                         \
        for (int kk = 0; kk < 64; kk += 16) {                                     \
            unsigned a[4];                                                        \
            a[0] = lds_u32(&kbuf[s_][wm + g][kk + tg * 2]);                       \
            a[1] = lds_u32(&kbuf[s_][wm + g + 8][kk + tg * 2]);                   \
            a[2] = lds_u32(&kbuf[s_][wm + g][kk + tg * 2 + 8]);                   \
            a[3] = lds_u32(&kbuf[s_][wm + g + 8][kk + tg * 2 + 8]);               \
            _Pragma("unroll")                                                     \
            for (int in_ = 0; in_ < 2; in_++) {                                   \
                unsigned bb[2];                                                   \
                bb[0] = lds_u32(&qbuf[s_][wn + in_ * 8 + g][kk + tg * 2]);        \
                bb[1] = lds_u32(&qbuf[s_][wn + in_ * 8 + g][kk + tg * 2 + 8]);    \
                mma16(acc[in_], a, bb);                                           \
            }                                                                     \
        }                                                                         \
        sc[h][0] = __floats2half2_rn(acc[0][0], acc[0][1]);                       \
        sc[h][1] = __floats2half2_rn(acc[0][2], acc[0][3]);                       \
        sc[h][2] = __floats2half2_rn(acc[1][0], acc[1][1]);                       \
        sc[h][3] = __floats2half2_rn(acc[1][2], acc[1][3]);                       \
    }

    ISSUE(0); ISSUE(1); ISSUE(2); ISSUE(3);
    cpwait2();
    __syncthreads();

#pragma unroll
    for (int p = 0; p < 6; p++) {
        COMPUTE(2 * p);
        COMPUTE(2 * p + 1);
        __syncthreads();
        if (p + 2 < 6) {
            ISSUE(2 * p + 4);
            ISSUE(2 * p + 5);
        } else {
            cpcommit(); cpcommit();
        }
        cpwait2();
        __syncthreads();
    }
#undef ISSUE
#undef COMPUTE

    // LN across heads, in registers (overwrite sc with LN'd values)
    float gm[NH], be[NH];
#pragma unroll
    for (int h = 0; h < NH; h++) { gm[h] = gamma[h]; be[h] = beta[h]; }
#pragma unroll
    for (int p = 0; p < 4; p++) {
        float mux = 0.f, muy = 0.f;
#pragma unroll
        for (int h = 0; h < NH; h++) {
            float2 f = __half22float2(sc[h][p]);
            mux += f.x; muy += f.y;
        }
        mux *= (1.f / NH); muy *= (1.f / NH);
        float varx = 0.f, vary = 0.f;
#pragma unroll
        for (int h = 0; h < NH; h++) {
            float2 f = __half22float2(sc[h][p]);
            float dx = f.x - mux, dy = f.y - muy;
            varx += dx * dx; vary += dy * dy;
        }
        float rsx = rsqrtf(varx * (1.f / NH) + 1e-5f);
        float rsy = rsqrtf(vary * (1.f / NH) + 1e-5f);
#pragma unroll
        for (int h = 0; h < NH; h++) {
            float2 f = __half22float2(sc[h][p]);
            sc[h][p] = __floats2half2_rn((f.x - mux) * rsx * gm[h] + be[h],
                                         (f.y - muy) * rsy * gm[h] + be[h]);
        }
    }

    // staged, coalesced output: per head stage 64x32 tile in smem, write 64B rows
    __half* ob = att + (long long)b * NH * LL + (long long)I0 * L + J0;
    const int trow = tid >> 2, tcol = (tid & 3) * 8;
#pragma unroll
    for (int h = 0; h < NH; h++) {
        __syncthreads();
#pragma unroll
        for (int p = 0; p < 4; p++) {
            int i = wm + g + ((p & 1) ? 8 : 0);
            int j = wn + ((p >> 1) ? 8 : 0) + tg * 2;
            *(__half2*)&tile[i][j] = sc[h][p];
        }
        __syncthreads();
        *(uint4*)&ob[(long long)h * LL + (long long)trow * L + tcol] =
            *(uint4*)&tile[trow][tcol];
    }
}

// ---------------- 4. fused softmax + colsum + att@V (fp16 out) ----------------
#define SMATTV_SMEM (64*520*2 + 2*64*72*2)   // 84992
__global__ void __launch_bounds__(256)
smattv_k(const __half* __restrict__ att, const __half* __restrict__ vt,
         __half* __restrict__ out, float* __restrict__ col) {
    extern __shared__ __align__(16) char smem_raw[];
    __half (*satt)[520] = (__half(*)[520])smem_raw;
    __half (*vbuf)[64][72] = (__half(*)[64][72])(smem_raw + 64*520*2);

    const int tid = threadIdx.x;
    const int wid = tid >> 5, lane = tid & 31;
    const int g = lane >> 2, tg = lane & 3;
    const int wm = (wid >> 1) * 16, wn = (wid & 1) * 32;
    const int I0 = blockIdx.x * 64;
    const int z = blockIdx.y;
    const int b = z / NH, h = z % NH;

    const __half* abase = att + (long long)z * LL + (long long)I0 * L;
    const __half* vbase = vt + (long long)z * HD * L;

#pragma unroll
    for (int c = 0; c < 16; c++) {
        int idx = tid + c * 256;
        int r = idx >> 6, jc = idx & 63;
        cpasync16(&satt[r][jc * 8], abase + (long long)r * L + jc * 8);
    }
    cpcommit();

#define ISSUEV(kt, s)                                                            \
    {                                                                            \
        _Pragma("unroll")                                                        \
        for (int c = 0; c < 2; c++) {                                            \
            int idx = tid + c * 256;                                             \
            int r = idx >> 3, jc = idx & 7;                                      \
            cpasync16(&vbuf[s][r][jc * 8], vbase + (long long)r * L + (kt) * 64 + jc * 8); \
        }                                                                        \
    }
    ISSUEV(0, 0); cpcommit();
    cpwait1();
    __syncthreads();

    for (int k = 0; k < 8; k++) {
        int r = wid * 8 + k;
        float v[16];
        float m = -1e30f;
#pragma unroll
        for (int q = 0; q < 8; q++) {
            float2 f = __half22float2(*(__half2*)&satt[r][lane * 2 + q * 64]);
            v[2 * q] = f.x; v[2 * q + 1] = f.y;
            m = fmaxf(m, fmaxf(f.x, f.y));
        }
#pragma unroll
        for (int o = 16; o; o >>= 1) m = fmaxf(m, __shfl_xor_sync(0xffffffffu, m, o));
        float s = 0.f;
#pragma unroll
        for (int q = 0; q < 16; q++) { v[q] = __expf(v[q] - m); s += v[q]; }
#pragma unroll
        for (int o = 16; o; o >>= 1) s += __shfl_xor_sync(0xffffffffu, s, o);
        float inv = 1.f / s;
#pragma unroll
        for (int q = 0; q < 8; q++)
            *(__half2*)&satt[r][lane * 2 + q * 64] =
                __floats2half2_rn(v[2 * q] * inv, v[2 * q + 1] * inv);
    }
    __syncthreads();

    {
        int j = tid * 2;
        float c0 = 0.f, c1 = 0.f;
#pragma unroll 8
        for (int r = 0; r < 64; r++) {
            float2 f = __half22float2(*(__half2*)&satt[r][j]);
            c0 += f.x; c1 += f.y;
        }
        atomicAdd(&col[b * L + j], c0 * (1.f / NH));
        atomicAdd(&col[b * L + j + 1], c1 * (1.f / NH));
    }

    float acc[4][4] = {};
    int rs = 0;
    for (int kt = 0; kt < 8; kt++) {
        if (kt + 1 < 8) ISSUEV(kt + 1, rs ^ 1);
        cpcommit();
        cpwait1();
        __syncthreads();
#pragma unroll
        for (int kk = 0; kk < 64; kk += 16) {
            unsigned a[4];
            int kc = kt * 64 + kk + tg * 2;
            a[0] = lds_u32(&satt[wm + g][kc]);
            a[1] = lds_u32(&satt[wm + g + 8][kc]);
            a[2] = lds_u32(&satt[wm + g][kc + 8]);
            a[3] = lds_u32(&satt[wm + g + 8][kc + 8]);
#pragma unroll
            for (int in_ = 0; in_ < 4; in_++) {
                unsigned bb[2];
                bb[0] = lds_u32(&vbuf[rs][wn + in_ * 8 + g][kk + tg * 2]);
                bb[1] = lds_u32(&vbuf[rs][wn + in_ * 8 + g][kk + tg * 2 + 8]);
                mma16(acc[in_], a, bb);
            }
        }
        rs ^= 1;
        __syncthreads();
    }
#undef ISSUEV

    __half* ob = out + ((long long)b * L + I0) * D + h * HD;
#pragma unroll
    for (int in_ = 0; in_ < 4; in_++) {
        int c = wn + in_ * 8 + tg * 2;
        *(__half2*)&ob[(long long)(wm + g) * D + c] =
            __floats2half2_rn(acc[in_][0], acc[in_][1]);
        *(__half2*)&ob[(long long)(wm + g + 8) * D + c] =
            __floats2half2_rn(acc[in_][2], acc[in_][3]);
    }
}

// ---------------- 5. per-token class probs (fp16 activations AND weights) ----------------
__global__ void probs_k(const __half* __restrict__ out, const __half* __restrict__ Wout,
                        const float* __restrict__ bout, float* __restrict__ probs) {
    int bl = blockIdx.x;
    int warp = threadIdx.x >> 5, lane = threadIdx.x & 31;
    __shared__ float s[NC];
    __shared__ float mx, sum;
    const __half* row = out + (long long)bl * D;
#pragma unroll
    for (int cc = 0; cc < 4; cc++) {
        int c = warp * 4 + cc;
        const __half* w = Wout + c * D;
        float acc = 0.f;
        for (int k = lane * 2; k < D; k += 64) {
            float2 f = __half22float2(*(const __half2*)(row + k));
            float2 ww = __half22float2(*(const __half2*)(w + k));
            acc += f.x * ww.x + f.y * ww.y;
        }
#pragma unroll
        for (int o = 16; o; o >>= 1) acc += __shfl_down_sync(0xffffffffu, acc, o);
        if (lane == 0) s[c] = acc + bout[c];
    }
    __syncthreads();
    if (threadIdx.x == 0) {
        float m = -1e30f;
        for (int c = 0; c < NC; c++) m = fmaxf(m, s[c]);
        float ss = 0.f;
        for (int c = 0; c < NC; c++) ss += __expf(s[c] - m);
        mx = m; sum = ss;
    }
    __syncthreads();
    if (threadIdx.x < NC)
        probs[(long long)bl * NC + threadIdx.x] = __expf(s[threadIdx.x] - mx) / sum;
}

// ---------------- 6. fused token weights softmax + final reduce ----------------
__global__ void __launch_bounds__(512)
wfinal_k(const int* __restrict__ ids, const float* __restrict__ col,
         const float* __restrict__ probs, float* __restrict__ dout, int first) {
    int b = blockIdx.x, l = threadIdx.x;
    int wid = l >> 5, lane = l & 31;
    __shared__ float red[512];
    __shared__ float psum[16][NC];

    float w = (ids[b * L + l] != 0 ? 1.f : 0.f) * col[b * L + l];
    red[l] = w;
    __syncthreads();
    for (int o = 256; o; o >>= 1) { if (l < o) red[l] = fmaxf(red[l], red[l + o]); __syncthreads(); }
    float mxv = red[0];
    __syncthreads();
    float e = __expf(w - mxv);
    red[l] = e;
    __syncthreads();
    for (int o = 256; o; o >>= 1) { if (l < o) red[l] += red[l + o]; __syncthreads(); }
    float wg = e / red[0];

    const float* pb = probs + (long long)(b * L + l) * NC;
    float myp[NC];
#pragma unroll
    for (int c = 0; c < NC; c++) myp[c] = wg * pb[c];
#pragma unroll
    for (int c = 0; c < NC; c++) {
        float v = myp[c];
#pragma unroll
        for (int o = 16; o; o >>= 1) v += __shfl_xor_sync(0xffffffffu, v, o);
        if (lane == 0) psum[wid][c] = v;
    }
    __syncthreads();
    if (l < NC) {
        float s = 0.f;
#pragma unroll
        for (int q = 0; q < 16; q++) s += psum[q][l];
        float v = 0.5f * s;
        dout[b * NC + l] = first ? v : dout[b * NC + l] + v;
    }
}

// ---------------- launch ----------------
extern "C" void kernel_launch(void* const* d_in, const int* in_sizes, int n_in,
                              void* d_out, int out_size) {
    (void)in_sizes; (void)n_in; (void)out_size;
    const int*   ids   = (const int*)d_in[0];
    const float* wv    = (const float*)d_in[1];
    const float* emb   = (const float*)d_in[2];
    const float* W_t   = (const float*)d_in[3];
    const float* b_t   = (const float*)d_in[4];
    const float* gam_t = (const float*)d_in[5];
    const float* bet_t = (const float*)d_in[6];
    const float* Wo_t  = (const float*)d_in[7];
    const float* bo_t  = (const float*)d_in[8];
    const float* W_h   = (const float*)d_in[9];
    const float* b_h   = (const float*)d_in[10];
    const float* gam_h = (const float*)d_in[11];
    const float* bet_h = (const float*)d_in[12];
    const float* Wo_h  = (const float*)d_in[13];
    const float* bo_h  = (const float*)d_in[14];
    float* out = (float*)d_out;

    __half *px, *pwt, *pwh, *pwv, *pwot, *pwoh, *patt16, *pqn, *pkn, *pvt, *pout;
    __half *patt16_2, *pqn2, *pkn2, *pvt2, *pout2;
    float *pprobs, *pcol, *pprobs2, *pcol2;
    cudaGetSymbolAddress((void**)&px, g_x);
    cudaGetSymbolAddress((void**)&pwt, g_wt16);
    cudaGetSymbolAddress((void**)&pwh, g_wh16);
    cudaGetSymbolAddress((void**)&pwv, g_wv16);
    cudaGetSymbolAddress((void**)&pwot, g_wot16);
    cudaGetSymbolAddress((void**)&pwoh, g_woh16);
    cudaGetSymbolAddress((void**)&patt16, g_att16);
    cudaGetSymbolAddress((void**)&pqn, g_qn);
    cudaGetSymbolAddress((void**)&pkn, g_kn);
    cudaGetSymbolAddress((void**)&pvt, g_vt);
    cudaGetSymbolAddress((void**)&pout, g_out);
    cudaGetSymbolAddress((void**)&pprobs, g_probs);
    cudaGetSymbolAddress((void**)&pcol, g_col);
    cudaGetSymbolAddress((void**)&patt16_2, g_att16_2);
    cudaGetSymbolAddress((void**)&pqn2, g_qn2);
    cudaGetSymbolAddress((void**)&pkn2, g_kn2);
    cudaGetSymbolAddress((void**)&pvt2, g_vt2);
    cudaGetSymbolAddress((void**)&pout2, g_out2);
    cudaGetSymbolAddress((void**)&pprobs2, g_probs2);
    cudaGetSymbolAddress((void**)&pcol2, g_col2);

    cudaFuncSetAttribute(smattv_k, cudaFuncAttributeMaxDynamicSharedMemorySize, SMATTV_SMEM);
    cudaFuncSetAttribute(attln5_k, cudaFuncAttributeMaxDynamicSharedMemorySize, ATTLN5_SMEM);

    dim3 proj_grid(D3 / 128, BL / 128);
    dim3 attln_grid(L / 32, L / 64, Bsz);
    dim3 smattv_grid(L / 64, BH);

    // Fork a second stream for the independent hidden branch (graph-capturable;
    // created per call, intentionally not destroyed — see R7 notes).
    cudaStream_t s2;
    cudaStreamCreateWithFlags(&s2, cudaStreamNonBlocking);
    cudaEvent_t evFork, evJoin;
    cudaEventCreateWithFlags(&evFork, cudaEventDisableTiming);
    cudaEventCreateWithFlags(&evJoin, cudaEventDisableTiming);

    cudaEventRecord(evFork, 0);
    cudaStreamWaitEvent(s2, evFork, 0);

    // ===== token branch (main stream) =====
    embed_leaky_k<<<BL, 192>>>(ids, emb, px);
    convpad_k<<<D3, 192>>>(W_t, pwt, D, D);
    convpad_k<<<NC, 192>>>(Wo_t, pwot, D, D);
    projsplit_k<<<proj_grid, 256>>>(px, D, pwt, D, b_t, pqn, pkn, pvt, pcol, D);
    attln5_k<<<attln_grid, 256, ATTLN5_SMEM>>>(pkn, pqn, patt16, gam_t, bet_t);
    smattv_k<<<smattv_grid, 256, SMATTV_SMEM>>>(patt16, pvt, pout, pcol);
    probs_k<<<BL, 160>>>(pout, pwot, bo_t, pprobs);
    wfinal_k<<<Bsz, 512>>>(ids, pcol, pprobs, out, 1);

    // ===== hidden / word-vector branch (stream s2) =====
    convpad_k<<<D3, 128, 0, s2>>>(W_h, pwh, 300, KH);
    convpad_k<<<BL, 128, 0, s2>>>(wv, pwv, 300, KH);
    convpad_k<<<NC, 128, 0, s2>>>(Wo_h, pwoh, D, D);
    projsplit_k<<<proj_grid, 256, 0, s2>>>(pwv, KH, pwh, KH, b_h, pqn2, pkn2, pvt2, pcol2, KH);
    attln5_k<<<attln_grid, 256, ATTLN5_SMEM, s2>>>(pkn2, pqn2, patt16_2, gam_h, bet_h);
    smattv_k<<<smattv_grid, 256, SMATTV_SMEM, s2>>>(patt16_2, pvt2, pout2, pcol2);
    probs_k<<<BL, 160, 0, s2>>>(pout2, pwoh, bo_h, pprobs2);

    // join: hidden-branch results folded into d_out on the main stream
    cudaEventRecord(evJoin, s2);
    cudaStreamWaitEvent(0, evJoin, 0);
    wfinal_k<<<Bsz, 512>>>(ids, pcol2, pprobs2, out, 0);
}

// round 16
// speedup vs baseline: 1.1283x; 1.0269x over previous
#include <cuda_runtime.h>
#include <cuda_fp16.h>
#include <math.h>

#define Bsz 16
#define L   512
#define NH  12
#define HD  64
#define D   768
#define D3  2304
#define NC  20
#define BL  (Bsz*L)      // 8192
#define BH  (Bsz*NH)     // 192
#define LL  (L*L)        // 262144
#define KH  320          // padded K for hidden branch (300 -> 320)

// ---------------- scratch (allocation-free) ----------------
// token branch
__device__ __half g_x[(size_t)BL*D];
__device__ __half g_wt16[(size_t)D3*D];
__device__ __half g_wot16[(size_t)NC*D];
__device__ __half g_att16[(size_t)BH*LL];
__device__ __half g_qn[(size_t)BH*L*HD];
__device__ __half g_kn[(size_t)BH*L*HD];
__device__ __half g_vt[(size_t)BH*HD*L];      // V transposed [z][d][l]
__device__ __half g_out[(size_t)BL*D];
__device__ float  g_probs[(size_t)BL*NC];
__device__ float  g_col[BL];
// hidden branch (independent copies so both branches run concurrently)
__device__ __half g_wh16[(size_t)D3*KH];
__device__ __half g_wv16[(size_t)BL*KH];
__device__ __half g_woh16[(size_t)NC*D];
__device__ __half g_att16_2[(size_t)BH*LL];
__device__ __half g_qn2[(size_t)BH*L*HD];
__device__ __half g_kn2[(size_t)BH*L*HD];
__device__ __half g_vt2[(size_t)BH*HD*L];
__device__ __half g_out2[(size_t)BL*D];
__device__ float  g_probs2[(size_t)BL*NC];
__device__ float  g_col2[BL];

__device__ __forceinline__ float lrelu(float x) { return x >= 0.f ? x : 0.01f * x; }

__device__ __forceinline__ void mma16(float c[4], const unsigned a[4], const unsigned b[2]) {
    asm volatile(
        "mma.sync.aligned.m16n8k16.row.col.f32.f16.f16.f32 "
        "{%0,%1,%2,%3},{%4,%5,%6,%7},{%8,%9},{%0,%1,%2,%3};"
        : "+f"(c[0]), "+f"(c[1]), "+f"(c[2]), "+f"(c[3])
        : "r"(a[0]), "r"(a[1]), "r"(a[2]), "r"(a[3]), "r"(b[0]), "r"(b[1]));
}
__device__ __forceinline__ void ldsm4(unsigned r[4], const __half* p) {
    unsigned addr = (unsigned)__cvta_generic_to_shared(p);
    asm volatile("ldmatrix.sync.aligned.m8n8.x4.shared.b16 {%0,%1,%2,%3}, [%4];"
        : "=r"(r[0]), "=r"(r[1]), "=r"(r[2]), "=r"(r[3]) : "r"(addr));
}
__device__ __forceinline__ void cpasync16(void* smem, const void* gmem) {
    unsigned s = (unsigned)__cvta_generic_to_shared(smem);
    asm volatile("cp.async.cg.shared.global [%0], [%1], 16;\n" :: "r"(s), "l"(gmem));
}
__device__ __forceinline__ void cpcommit() { asm volatile("cp.async.commit_group;\n"); }
__device__ __forceinline__ void cpwait1()  { asm volatile("cp.async.wait_group 1;\n"); }
__device__ __forceinline__ void cpwait2()  { asm volatile("cp.async.wait_group 2;\n"); }

// ---------------- 0. fp32 -> fp16 (optionally K-padded rows) ----------------
__global__ void convpad_k(const float* __restrict__ src, __half* __restrict__ dst,
                          int K, int KP) {
    long long row = blockIdx.x;
    for (int k4 = threadIdx.x * 4; k4 < KP; k4 += blockDim.x * 4) {
        float4 v = (k4 + 4 <= K) ? *(const float4*)(src + row * K + k4)
                                 : make_float4(k4 < K ? src[row * K + k4] : 0.f,
                                               k4 + 1 < K ? src[row * K + k4 + 1] : 0.f,
                                               k4 + 2 < K ? src[row * K + k4 + 2] : 0.f,
                                               k4 + 3 < K ? src[row * K + k4 + 3] : 0.f);
        *(__half2*)(dst + row * KP + k4)     = __floats2half2_rn(v.x, v.y);
        *(__half2*)(dst + row * KP + k4 + 2) = __floats2half2_rn(v.z, v.w);
    }
}

// ---------------- 1. embedding + leaky -> fp16 ----------------
__global__ void embed_leaky_k(const int* __restrict__ ids, const float* __restrict__ emb,
                              __half* __restrict__ x) {
    int bl = blockIdx.x;
    long long id = ids[bl];
    const float* src = emb + id * D;
    __half* dst = x + (long long)bl * D;
    for (int k4 = threadIdx.x * 4; k4 < D; k4 += blockDim.x * 4) {
        float4 v = *(const float4*)(src + k4);
        *(__half2*)(dst + k4)     = __floats2half2_rn(lrelu(v.x), lrelu(v.y));
        *(__half2*)(dst + k4 + 2) = __floats2half2_rn(lrelu(v.z), lrelu(v.w));
    }
}

// ---------------- 2. fused proj GEMM + QKV split + cosine-norm + V transpose ----------------
__global__ void __launch_bounds__(256)
projsplit_k(const __half* __restrict__ A, int lda,
            const __half* __restrict__ W, int ldb,
            const float* __restrict__ bias,
            __half* __restrict__ qn, __half* __restrict__ kn,
            __half* __restrict__ vt, float* __restrict__ col, int K) {
    constexpr int BM = 128, BN = 128, WM = 32, WN = 64, BK = 32, PAD = 8, STG = 3;
    constexpr int IM = 2, IN = 8;

    __shared__ __align__(16) __half As[STG][BM][BK + PAD];
    __shared__ __align__(16) __half Bs[STG][BN][BK + PAD];

    const int tid = threadIdx.x;
    const int wid = tid >> 5, lane = tid & 31;
    const int g = lane >> 2, tg = lane & 3;
    const int sub = lane >> 3, lrow = lane & 7;
    const int wm = (wid >> 1) * WM, wn = (wid & 1) * WN;

    const __half* Ab = A + (long long)blockIdx.y * BM * lda;
    const __half* Bb = W + (long long)blockIdx.x * BN * ldb;

    const int ktiles = K / BK;
    float acc[IM][IN][4] = {};

    auto issue = [&](int t, int s) {
        int k0 = t * BK;
#pragma unroll
        for (int c = 0; c < 2; c++) {
            int idx = tid + c * 256;
            int row = idx >> 2, cq = idx & 3;
            cpasync16(&As[s][row][cq * 8], Ab + (long long)row * lda + k0 + cq * 8);
        }
#pragma unroll
        for (int c = 0; c < 2; c++) {
            int idx = tid + c * 256;
            int row = idx >> 2, cq = idx & 3;
            cpasync16(&Bs[s][row][cq * 8], Bb + (long long)row * ldb + k0 + cq * 8);
        }
    };

    issue(0, 0); cpcommit();
    if (ktiles > 1) issue(1, 1);
    cpcommit();
    cpwait1();
    __syncthreads();

    int rs = 0;
    for (int t = 0; t < ktiles; t++) {
#pragma unroll
        for (int kk = 0; kk < BK; kk += 16) {
            unsigned a[IM][4], b[IN][2];
#pragma unroll
            for (int im = 0; im < IM; im++)
                ldsm4(a[im], &As[rs][wm + im * 16 + (sub & 1) * 8 + lrow][kk + (sub >> 1) * 8]);
#pragma unroll
            for (int inp = 0; inp < IN / 2; inp++) {
                unsigned tr[4];
                ldsm4(tr, &Bs[rs][wn + inp * 16 + (sub >> 1) * 8 + lrow][kk + (sub & 1) * 8]);
                b[2 * inp][0] = tr[0]; b[2 * inp][1] = tr[1];
                b[2 * inp + 1][0] = tr[2]; b[2 * inp + 1][1] = tr[3];
            }
#pragma unroll
            for (int im = 0; im < IM; im++)
#pragma unroll
                for (int in_ = 0; in_ < IN; in_++)
                    mma16(acc[im][in_], a[im], b[in_]);
        }
        if (t + 2 < ktiles) issue(t + 2, (rs + 2) % STG);
        cpcommit();
        cpwait1();
        __syncthreads();
        rs = (rs + 1) % STG;
    }

    const int sec  = blockIdx.x / 6;                       // 0=Q, 1=K, 2=V
    const int m0   = blockIdx.y * BM;
    const int b    = m0 / L;
    const int l0   = m0 % L;

    if (blockIdx.x == 12 && tid < 128) col[b * L + l0 + tid] = 0.f;

#pragma unroll
    for (int im = 0; im < IM; im++)
#pragma unroll
        for (int in_ = 0; in_ < IN; in_++) {
            int cc = blockIdx.x * BN + wn + in_ * 8 + tg * 2;
            float b0 = bias[cc], b1 = bias[cc + 1];
            acc[im][in_][0] = lrelu(acc[im][in_][0] + b0);
            acc[im][in_][1] = lrelu(acc[im][in_][1] + b1);
            acc[im][in_][2] = lrelu(acc[im][in_][2] + b0);
            acc[im][in_][3] = lrelu(acc[im][in_][3] + b1);
        }

    if (sec < 2) {
        const int hloc = (blockIdx.x % 6) * 2 + (wn >> 6);
        const long long z = (long long)b * NH + hloc;
        __half* dst = (sec == 0) ? qn : kn;
#pragma unroll
        for (int im = 0; im < IM; im++) {
            float ss0 = 0.f, ss1 = 0.f;
#pragma unroll
            for (int in_ = 0; in_ < IN; in_++) {
                ss0 += acc[im][in_][0] * acc[im][in_][0] + acc[im][in_][1] * acc[im][in_][1];
                ss1 += acc[im][in_][2] * acc[im][in_][2] + acc[im][in_][3] * acc[im][in_][3];
            }
            ss0 += __shfl_xor_sync(0xffffffffu, ss0, 1);
            ss0 += __shfl_xor_sync(0xffffffffu, ss0, 2);
            ss1 += __shfl_xor_sync(0xffffffffu, ss1, 1);
            ss1 += __shfl_xor_sync(0xffffffffu, ss1, 2);
            float r0 = 1.f / fmaxf(sqrtf(ss0), 1e-8f);
            float r1 = 1.f / fmaxf(sqrtf(ss1), 1e-8f);
            int lA = l0 + wm + im * 16 + g;
            int lB = lA + 8;
#pragma unroll
            for (int in_ = 0; in_ < IN; in_++) {
                int dcol = in_ * 8 + tg * 2;
                *(__half2*)&dst[(z * L + lA) * HD + dcol] =
                    __floats2half2_rn(acc[im][in_][0] * r0, acc[im][in_][1] * r0);
                *(__half2*)&dst[(z * L + lB) * HD + dcol] =
                    __floats2half2_rn(acc[im][in_][2] * r1, acc[im][in_][3] * r1);
            }
        }
    } else {
        __half (*sv)[136] = (__half(*)[136])Bs;
#pragma unroll
        for (int p = 0; p < 2; p++) {
            __syncthreads();
            if ((wn >> 6) == p) {
#pragma unroll
                for (int im = 0; im < IM; im++)
#pragma unroll
                    for (int in_ = 0; in_ < IN; in_++) {
                        int d = in_ * 8 + tg * 2;
                        int l = wm + im * 16 + g;
                        sv[d][l]         = __float2half_rn(acc[im][in_][0]);
                        sv[d + 1][l]     = __float2half_rn(acc[im][in_][1]);
                        sv[d][l + 8]     = __float2half_rn(acc[im][in_][2]);
                        sv[d + 1][l + 8] = __float2half_rn(acc[im][in_][3]);
                    }
            }
            __syncthreads();
            long long z = (long long)b * NH + (blockIdx.x % 6) * 2 + p;
#pragma unroll
            for (int c = 0; c < 4; c++) {
                int idx = tid + c * 256;
                int d = idx >> 4, lc = (idx & 15) * 8;
                *(uint4*)(vt + (z * HD + d) * L + l0 + lc) = *(uint4*)&sv[d][lc];
            }
        }
    }
}

// ---------------- 3. fused scores + LN(heads): 2 heads/stage, ldmatrix, coalesced writes ----------------
#define ATTLN5_SMEM (4*64*72*2 + 4*32*72*2)   // 55296
__global__ void __launch_bounds__(256, 2)
attln5_k(const __half* __restrict__ kn, const __half* __restrict__ qn,
         __half* __restrict__ att, const float* __restrict__ gamma,
         const float* __restrict__ beta) {
    extern __shared__ __align__(16) char smraw[];
    __half (*kbuf)[64][72] = (__half(*)[64][72])smraw;
    __half (*qbuf)[32][72] = (__half(*)[32][72])(smraw + 4*64*72*2);
    __half (*tile)[40] = (__half(*)[40])smraw;   // aliases kbuf after compute

    const int tid = threadIdx.x;
    const int wid = tid >> 5, lane = tid & 31;
    const int g = lane >> 2, tg = lane & 3;
    const int sub = lane >> 3, lrow = lane & 7;
    const int wm = (wid >> 1) * 16, wn = (wid & 1) * 16;
    const int J0 = blockIdx.x * 32, I0 = blockIdx.y * 64, b = blockIdx.z;

    const __half* kb = kn + ((long long)b * NH * L + I0) * HD;
    const __half* qb = qn + ((long long)b * NH * L + J0) * HD;

    __half2 sc[NH][4];

#define ISSUE(h)                                                                  \
    {                                                                             \
        int s_ = (h) & 3;                                                         \
        long long hoff = (long long)(h) * L * HD;                                 \
        _Pragma("unroll")                                                         \
        for (int c = 0; c < 2; c++) {                                             \
            int idx = tid + c * 256;                                              \
            int r = idx >> 3, jc = idx & 7;                                       \
            cpasync16(&kbuf[s_][r][jc * 8], kb + hoff + (long long)r * HD + jc * 8); \
        }                                                                         \
        { int r = tid >> 3, jc = tid & 7;                                         \
          cpasync16(&qbuf[s_][r][jc * 8], qb + hoff + (long long)r * HD + jc * 8); } \
        cpcommit();                                                               \
    }

#define COMPUTE(h)                                                                \
    {                                                                             \
        int s_ = (h) & 3;                                                         \
        float acc[2][4] = {};                                                     \
        _Pragma("unroll")                                                         \
        for (int kk = 0; kk < 64; kk += 16) {                                     \
            unsigned a[4], bb[4];                                                 \
            ldsm4(a, &kbuf[s_][wm + (sub & 1) * 8 + lrow][kk + (sub >> 1) * 8]);  \
            ldsm4(bb, &qbuf[s_][wn + (sub >> 1) * 8 + lrow][kk + (sub & 1) * 8]); \
            mma16(acc[0], a, &bb[0]);                                             \
            mma16(acc[1], a, &bb[2]);                                             \
        }                                                                         \
        sc[h][0] = __floats2half2_rn(acc[0][0], acc[0][1]);                       \
        sc[h][1] = __floats2half2_rn(acc[0][2], acc[0][3]);                       \
        sc[h][2] = __floats2half2_rn(acc[1][0], acc[1][1]);                       \
        sc[h][3] = __floats2half2_rn(acc[1][2], acc[1][3]);                       \
    }

    ISSUE(0); ISSUE(1); ISSUE(2); ISSUE(3);
    cpwait2();
    __syncthreads();

#pragma unroll
    for (int p = 0; p < 6; p++) {
        COMPUTE(2 * p);
        COMPUTE(2 * p + 1);
        __syncthreads();
        if (p + 2 < 6) {
            ISSUE(2 * p + 4);
            ISSUE(2 * p + 5);
        } else {
            cpcommit(); cpcommit();
        }
        cpwait2();
        __syncthreads();
    }
#undef ISSUE
#undef COMPUTE

    // LN across heads, in registers (overwrite sc with LN'd values)
    float gm[NH], be[NH];
#pragma unroll
    for (int h = 0; h < NH; h++) { gm[h] = gamma[h]; be[h] = beta[h]; }
#pragma unroll
    for (int p = 0; p < 4; p++) {
        float mux = 0.f, muy = 0.f;
#pragma unroll
        for (int h = 0; h < NH; h++) {
            float2 f = __half22float2(sc[h][p]);
            mux += f.x; muy += f.y;
        }
        mux *= (1.f / NH); muy *= (1.f / NH);
        float varx = 0.f, vary = 0.f;
#pragma unroll
        for (int h = 0; h < NH; h++) {
            float2 f = __half22float2(sc[h][p]);
            float dx = f.x - mux, dy = f.y - muy;
            varx += dx * dx; vary += dy * dy;
        }
        float rsx = rsqrtf(varx * (1.f / NH) + 1e-5f);
        float rsy = rsqrtf(vary * (1.f / NH) + 1e-5f);
#pragma unroll
        for (int h = 0; h < NH; h++) {
            float2 f = __half22float2(sc[h][p]);
            sc[h][p] = __floats2half2_rn((f.x - mux) * rsx * gm[h] + be[h],
                                         (f.y - muy) * rsy * gm[h] + be[h]);
        }
    }

    // staged, coalesced output: per head stage 64x32 tile in smem, write 64B rows
    __half* ob = att + (long long)b * NH * LL + (long long)I0 * L + J0;
    const int trow = tid >> 2, tcol = (tid & 3) * 8;
#pragma unroll
    for (int h = 0; h < NH; h++) {
        __syncthreads();
#pragma unroll
        for (int p = 0; p < 4; p++) {
            int i = wm + g + ((p & 1) ? 8 : 0);
            int j = wn + ((p >> 1) ? 8 : 0) + tg * 2;
            *(__half2*)&tile[i][j] = sc[h][p];
        }
        __syncthreads();
        *(uint4*)&ob[(long long)h * LL + (long long)trow * L + tcol] =
            *(uint4*)&tile[trow][tcol];
    }
}

// ---------------- 4. fused softmax + colsum + att@V (ldmatrix, fp16 out) ----------------
#define SMATTV_SMEM (64*520*2 + 2*64*72*2)   // 84992
__global__ void __launch_bounds__(256)
smattv_k(const __half* __restrict__ att, const __half* __restrict__ vt,
         __half* __restrict__ out, float* __restrict__ col) {
    extern __shared__ __align__(16) char smem_raw[];
    __half (*satt)[520] = (__half(*)[520])smem_raw;
    __half (*vbuf)[64][72] = (__half(*)[64][72])(smem_raw + 64*520*2);

    const int tid = threadIdx.x;
    const int wid = tid >> 5, lane = tid & 31;
    const int g = lane >> 2, tg = lane & 3;
    const int sub = lane >> 3, lrow = lane & 7;
    const int wm = (wid >> 1) * 16, wn = (wid & 1) * 32;
    const int I0 = blockIdx.x * 64;
    const int z = blockIdx.y;
    const int b = z / NH, h = z % NH;

    const __half* abase = att + (long long)z * LL + (long long)I0 * L;
    const __half* vbase = vt + (long long)z * HD * L;

#pragma unroll
    for (int c = 0; c < 16; c++) {
        int idx = tid + c * 256;
        int r = idx >> 6, jc = idx & 63;
        cpasync16(&satt[r][jc * 8], abase + (long long)r * L + jc * 8);
    }
    cpcommit();

#define ISSUEV(kt, s)                                                            \
    {                                                                            \
        _Pragma("unroll")                                                        \
        for (int c = 0; c < 2; c++) {                                            \
            int idx = tid + c * 256;                                             \
            int r = idx >> 3, jc = idx & 7;                                      \
            cpasync16(&vbuf[s][r][jc * 8], vbase + (long long)r * L + (kt) * 64 + jc * 8); \
        }                                                                        \
    }
    ISSUEV(0, 0); cpcommit();
    cpwait1();
    __syncthreads();

    for (int k = 0; k < 8; k++) {
        int r = wid * 8 + k;
        float v[16];
        float m = -1e30f;
#pragma unroll
        for (int q = 0; q < 8; q++) {
            float2 f = __half22float2(*(__half2*)&satt[r][lane * 2 + q * 64]);
            v[2 * q] = f.x; v[2 * q + 1] = f.y;
            m = fmaxf(m, fmaxf(f.x, f.y));
        }
#pragma unroll
        for (int o = 16; o; o >>= 1) m = fmaxf(m, __shfl_xor_sync(0xffffffffu, m, o));
        float s = 0.f;
#pragma unroll
        for (int q = 0; q < 16; q++) { v[q] = __expf(v[q] - m); s += v[q]; }
#pragma unroll
        for (int o = 16; o; o >>= 1) s += __shfl_xor_sync(0xffffffffu, s, o);
        float inv = 1.f / s;
#pragma unroll
        for (int q = 0; q < 8; q++)
            *(__half2*)&satt[r][lane * 2 + q * 64] =
                __floats2half2_rn(v[2 * q] * inv, v[2 * q + 1] * inv);
    }
    __syncthreads();

    {
        int j = tid * 2;
        float c0 = 0.f, c1 = 0.f;
#pragma unroll 8
        for (int r = 0; r < 64; r++) {
            float2 f = __half22float2(*(__half2*)&satt[r][j]);
            c0 += f.x; c1 += f.y;
        }
        atomicAdd(&col[b * L + j], c0 * (1.f / NH));
        atomicAdd(&col[b * L + j + 1], c1 * (1.f / NH));
    }

    float acc[4][4] = {};
    int rs = 0;
    for (int kt = 0; kt < 8; kt++) {
        if (kt + 1 < 8) ISSUEV(kt + 1, rs ^ 1);
        cpcommit();
        cpwait1();
        __syncthreads();
#pragma unroll
        for (int kk = 0; kk < 64; kk += 16) {
            unsigned a[4], b0[4], b1[4];
            ldsm4(a, &satt[wm + (sub & 1) * 8 + lrow][kt * 64 + kk + (sub >> 1) * 8]);
            ldsm4(b0, &vbuf[rs][wn + (sub >> 1) * 8 + lrow][kk + (sub & 1) * 8]);
            ldsm4(b1, &vbuf[rs][wn + 16 + (sub >> 1) * 8 + lrow][kk + (sub & 1) * 8]);
            mma16(acc[0], a, &b0[0]);
            mma16(acc[1], a, &b0[2]);
            mma16(acc[2], a, &b1[0]);
            mma16(acc[3], a, &b1[2]);
        }
        rs ^= 1;
        __syncthreads();
    }
#undef ISSUEV

    __half* ob = out + ((long long)b * L + I0) * D + h * HD;
#pragma unroll
    for (int in_ = 0; in_ < 4; in_++) {
        int c = wn + in_ * 8 + tg * 2;
        *(__half2*)&ob[(long long)(wm + g) * D + c] =
            __floats2half2_rn(acc[in_][0], acc[in_][1]);
        *(__half2*)&ob[(long long)(wm + g + 8) * D + c] =
            __floats2half2_rn(acc[in_][2], acc[in_][3]);
    }
}

// ---------------- 5. per-token class probs (fp16 activations AND weights) ----------------
__global__ void probs_k(const __half* __restrict__ out, const __half* __restrict__ Wout,
                        const float* __restrict__ bout, float* __restrict__ probs) {
    int bl = blockIdx.x;
    int warp = threadIdx.x >> 5, lane = threadIdx.x & 31;
    __shared__ float s[NC];
    __shared__ float mx, sum;
    const __half* row = out + (long long)bl * D;
#pragma unroll
    for (int cc = 0; cc < 4; cc++) {
        int c = warp * 4 + cc;
        const __half* w = Wout + c * D;
        float acc = 0.f;
        for (int k = lane * 2; k < D; k += 64) {
            float2 f = __half22float2(*(const __half2*)(row + k));
            float2 ww = __half22float2(*(const __half2*)(w + k));
            acc += f.x * ww.x + f.y * ww.y;
        }
#pragma unroll
        for (int o = 16; o; o >>= 1) acc += __shfl_down_sync(0xffffffffu, acc, o);
        if (lane == 0) s[c] = acc + bout[c];
    }
    __syncthreads();
    if (threadIdx.x == 0) {
        float m = -1e30f;
        for (int c = 0; c < NC; c++) m = fmaxf(m, s[c]);
        float ss = 0.f;
        for (int c = 0; c < NC; c++) ss += __expf(s[c] - m);
        mx = m; sum = ss;
    }
    __syncthreads();
    if (threadIdx.x < NC)
        probs[(long long)bl * NC + threadIdx.x] = __expf(s[threadIdx.x] - mx) / sum;
}

// ---------------- 6. fused token weights softmax + final reduce ----------------
__global__ void __launch_bounds__(512)
wfinal_k(const int* __restrict__ ids, const float* __restrict__ col,
         const float* __restrict__ probs, float* __restrict__ dout, int first) {
    int b = blockIdx.x, l = threadIdx.x;
    int wid = l >> 5, lane = l & 31;
    __shared__ float red[512];
    __shared__ float psum[16][NC];

    float w = (ids[b * L + l] != 0 ? 1.f : 0.f) * col[b * L + l];
    red[l] = w;
    __syncthreads();
    for (int o = 256; o; o >>= 1) { if (l < o) red[l] = fmaxf(red[l], red[l + o]); __syncthreads(); }
    float mxv = red[0];
    __syncthreads();
    float e = __expf(w - mxv);
    red[l] = e;
    __syncthreads();
    for (int o = 256; o; o >>= 1) { if (l < o) red[l] += red[l + o]; __syncthreads(); }
    float wg = e / red[0];

    const float* pb = probs + (long long)(b * L + l) * NC;
    float myp[NC];
#pragma unroll
    for (int c = 0; c < NC; c++) myp[c] = wg * pb[c];
#pragma unroll
    for (int c = 0; c < NC; c++) {
        float v = myp[c];
#pragma unroll
        for (int o = 16; o; o >>= 1) v += __shfl_xor_sync(0xffffffffu, v, o);
        if (lane == 0) psum[wid][c] = v;
    }
    __syncthreads();
    if (l < NC) {
        float s = 0.f;
#pragma unroll
        for (int q = 0; q < 16; q++) s += psum[q][l];
        float v = 0.5f * s;
        dout[b * NC + l] = first ? v : dout[b * NC + l] + v;
    }
}

// ---------------- launch ----------------
extern "C" void kernel_launch(void* const* d_in, const int* in_sizes, int n_in,
                              void* d_out, int out_size) {
    (void)in_sizes; (void)n_in; (void)out_size;
    const int*   ids   = (const int*)d_in[0];
    const float* wv    = (const float*)d_in[1];
    const float* emb   = (const float*)d_in[2];
    const float* W_t   = (const float*)d_in[3];
    const float* b_t   = (const float*)d_in[4];
    const float* gam_t = (const float*)d_in[5];
    const float* bet_t = (const float*)d_in[6];
    const float* Wo_t  = (const float*)d_in[7];
    const float* bo_t  = (const float*)d_in[8];
    const float* W_h   = (const float*)d_in[9];
    const float* b_h   = (const float*)d_in[10];
    const float* gam_h = (const float*)d_in[11];
    const float* bet_h = (const float*)d_in[12];
    const float* Wo_h  = (const float*)d_in[13];
    const float* bo_h  = (const float*)d_in[14];
    float* out = (float*)d_out;

    __half *px, *pwt, *pwh, *pwv, *pwot, *pwoh, *patt16, *pqn, *pkn, *pvt, *pout;
    __half *patt16_2, *pqn2, *pkn2, *pvt2, *pout2;
    float *pprobs, *pcol, *pprobs2, *pcol2;
    cudaGetSymbolAddress((void**)&px, g_x);
    cudaGetSymbolAddress((void**)&pwt, g_wt16);
    cudaGetSymbolAddress((void**)&pwh, g_wh16);
    cudaGetSymbolAddress((void**)&pwv, g_wv16);
    cudaGetSymbolAddress((void**)&pwot, g_wot16);
    cudaGetSymbolAddress((void**)&pwoh, g_woh16);
    cudaGetSymbolAddress((void**)&patt16, g_att16);
    cudaGetSymbolAddress((void**)&pqn, g_qn);
    cudaGetSymbolAddress((void**)&pkn, g_kn);
    cudaGetSymbolAddress((void**)&pvt, g_vt);
    cudaGetSymbolAddress((void**)&pout, g_out);
    cudaGetSymbolAddress((void**)&pprobs, g_probs);
    cudaGetSymbolAddress((void**)&pcol, g_col);
    cudaGetSymbolAddress((void**)&patt16_2, g_att16_2);
    cudaGetSymbolAddress((void**)&pqn2, g_qn2);
    cudaGetSymbolAddress((void**)&pkn2, g_kn2);
    cudaGetSymbolAddress((void**)&pvt2, g_vt2);
    cudaGetSymbolAddress((void**)&pout2, g_out2);
    cudaGetSymbolAddress((void**)&pprobs2, g_probs2);
    cudaGetSymbolAddress((void**)&pcol2, g_col2);

    cudaFuncSetAttribute(smattv_k, cudaFuncAttributeMaxDynamicSharedMemorySize, SMATTV_SMEM);
    cudaFuncSetAttribute(attln5_k, cudaFuncAttributeMaxDynamicSharedMemorySize, ATTLN5_SMEM);

    dim3 proj_grid(D3 / 128, BL / 128);
    dim3 attln_grid(L / 32, L / 64, Bsz);
    dim3 smattv_grid(L / 64, BH);

    // Fork a second stream for the independent hidden branch (graph-capturable;
    // created per call, intentionally not destroyed — see R7 notes).
    cudaStream_t s2;
    cudaStreamCreateWithFlags(&s2, cudaStreamNonBlocking);
    cudaEvent_t evFork, evJoin;
    cudaEventCreateWithFlags(&evFork, cudaEventDisableTiming);
    cudaEventCreateWithFlags(&evJoin, cudaEventDisableTiming);

    cudaEventRecord(evFork, 0);
    cudaStreamWaitEvent(s2, evFork, 0);

    // ===== token branch (main stream) =====
    embed_leaky_k<<<BL, 192>>>(ids, emb, px);
    convpad_k<<<D3, 192>>>(W_t, pwt, D, D);
    convpad_k<<<NC, 192>>>(Wo_t, pwot, D, D);
    projsplit_k<<<proj_grid, 256>>>(px, D, pwt, D, b_t, pqn, pkn, pvt, pcol, D);
    attln5_k<<<attln_grid, 256, ATTLN5_SMEM>>>(pkn, pqn, patt16, gam_t, bet_t);
    smattv_k<<<smattv_grid, 256, SMATTV_SMEM>>>(patt16, pvt, pout, pcol);
    probs_k<<<BL, 160>>>(pout, pwot, bo_t, pprobs);
    wfinal_k<<<Bsz, 512>>>(ids, pcol, pprobs, out, 1);

    // ===== hidden / word-vector branch (stream s2) =====
    convpad_k<<<D3, 128, 0, s2>>>(W_h, pwh, 300, KH);
    convpad_k<<<BL, 128, 0, s2>>>(wv, pwv, 300, KH);
    convpad_k<<<NC, 128, 0, s2>>>(Wo_h, pwoh, D, D);
    projsplit_k<<<proj_grid, 256, 0, s2>>>(pwv, KH, pwh, KH, b_h, pqn2, pkn2, pvt2, pcol2, KH);
    attln5_k<<<attln_grid, 256, ATTLN5_SMEM, s2>>>(pkn2, pqn2, patt16_2, gam_h, bet_h);
    smattv_k<<<smattv_grid, 256, SMATTV_SMEM, s2>>>(patt16_2, pvt2, pout2, pcol2);
    probs_k<<<BL, 160, 0, s2>>>(pout2, pwoh, bo_h, pprobs2);

    // join: hidden-branch results folded into d_out on the main stream
    cudaEventRecord(evJoin, s2);
    cudaStreamWaitEvent(0, evJoin, 0);
    wfinal_k<<<Bsz, 512>>>(ids, pcol2, pprobs2, out, 0);
}

// round 17
// speedup vs baseline: 1.1628x; 1.0305x over previous
#include <cuda_runtime.h>
#include <cuda_fp16.h>
#include <math.h>

#define Bsz 16
#define L   512
#define NH  12
#define HD  64
#define D   768
#define D3  2304
#define NC  20
#define BL  (Bsz*L)      // 8192
#define BH  (Bsz*NH)     // 192
#define LL  (L*L)        // 262144
#define KH  320          // padded K for hidden branch (300 -> 320)

// ---------------- scratch (allocation-free) ----------------
// token branch
__device__ __half g_x[(size_t)BL*D];
__device__ __half g_wt16[(size_t)D3*D];
__device__ __half g_wot16[(size_t)NC*D];
__device__ __half g_att16[(size_t)BH*LL];
__device__ __half g_qn[(size_t)BH*L*HD];
__device__ __half g_kn[(size_t)BH*L*HD];
__device__ __half g_vt[(size_t)BH*HD*L];      // V transposed [z][d][l]
__device__ __half g_out[(size_t)BL*D];
__device__ float  g_probs[(size_t)BL*NC];
__device__ float  g_col[BL];
// hidden branch (independent copies so both branches run concurrently)
__device__ __half g_wh16[(size_t)D3*KH];
__device__ __half g_wv16[(size_t)BL*KH];
__device__ __half g_woh16[(size_t)NC*D];
__device__ __half g_att16_2[(size_t)BH*LL];
__device__ __half g_qn2[(size_t)BH*L*HD];
__device__ __half g_kn2[(size_t)BH*L*HD];
__device__ __half g_vt2[(size_t)BH*HD*L];
__device__ __half g_out2[(size_t)BL*D];
__device__ float  g_probs2[(size_t)BL*NC];
__device__ float  g_col2[BL];

__device__ __forceinline__ float lrelu(float x) { return x >= 0.f ? x : 0.01f * x; }

__device__ __forceinline__ void mma16(float c[4], const unsigned a[4], const unsigned b[2]) {
    asm volatile(
        "mma.sync.aligned.m16n8k16.row.col.f32.f16.f16.f32 "
        "{%0,%1,%2,%3},{%4,%5,%6,%7},{%8,%9},{%0,%1,%2,%3};"
        : "+f"(c[0]), "+f"(c[1]), "+f"(c[2]), "+f"(c[3])
        : "r"(a[0]), "r"(a[1]), "r"(a[2]), "r"(a[3]), "r"(b[0]), "r"(b[1]));
}
__device__ __forceinline__ void ldsm4(unsigned r[4], const __half* p) {
    unsigned addr = (unsigned)__cvta_generic_to_shared(p);
    asm volatile("ldmatrix.sync.aligned.m8n8.x4.shared.b16 {%0,%1,%2,%3}, [%4];"
        : "=r"(r[0]), "=r"(r[1]), "=r"(r[2]), "=r"(r[3]) : "r"(addr));
}
__device__ __forceinline__ void cpasync16(void* smem, const void* gmem) {
    unsigned s = (unsigned)__cvta_generic_to_shared(smem);
    asm volatile("cp.async.cg.shared.global [%0], [%1], 16;\n" :: "r"(s), "l"(gmem));
}
__device__ __forceinline__ void cpcommit() { asm volatile("cp.async.commit_group;\n"); }
__device__ __forceinline__ void cpwait1()  { asm volatile("cp.async.wait_group 1;\n"); }
__device__ __forceinline__ void cpwait2()  { asm volatile("cp.async.wait_group 2;\n"); }

// ---------------- 0. fp32 -> fp16 (optionally K-padded rows) ----------------
__global__ void convpad_k(const float* __restrict__ src, __half* __restrict__ dst,
                          int K, int KP) {
    long long row = blockIdx.x;
    for (int k4 = threadIdx.x * 4; k4 < KP; k4 += blockDim.x * 4) {
        float4 v = (k4 + 4 <= K) ? *(const float4*)(src + row * K + k4)
                                 : make_float4(k4 < K ? src[row * K + k4] : 0.f,
                                               k4 + 1 < K ? src[row * K + k4 + 1] : 0.f,
                                               k4 + 2 < K ? src[row * K + k4 + 2] : 0.f,
                                               k4 + 3 < K ? src[row * K + k4 + 3] : 0.f);
        *(__half2*)(dst + row * KP + k4)     = __floats2half2_rn(v.x, v.y);
        *(__half2*)(dst + row * KP + k4 + 2) = __floats2half2_rn(v.z, v.w);
    }
}

// ---------------- 1. embedding + leaky -> fp16 ----------------
__global__ void embed_leaky_k(const int* __restrict__ ids, const float* __restrict__ emb,
                              __half* __restrict__ x) {
    int bl = blockIdx.x;
    long long id = ids[bl];
    const float* src = emb + id * D;
    __half* dst = x + (long long)bl * D;
    for (int k4 = threadIdx.x * 4; k4 < D; k4 += blockDim.x * 4) {
        float4 v = *(const float4*)(src + k4);
        *(__half2*)(dst + k4)     = __floats2half2_rn(lrelu(v.x), lrelu(v.y));
        *(__half2*)(dst + k4 + 2) = __floats2half2_rn(lrelu(v.z), lrelu(v.w));
    }
}

// ---------------- 2. fused proj GEMM + QKV split + cosine-norm + V transpose ----------------
// BK=64, 3-stage cp.async pipeline (dynamic smem 110.6 KB, 2 CTAs/SM)
#define PROJ_BK   64
#define PROJ_PAD  8
#define PROJ_STG  3
#define PROJ_SMEM (PROJ_STG * 2 * 128 * (PROJ_BK + PROJ_PAD) * 2)   // 110592
__global__ void __launch_bounds__(256)
projsplit_k(const __half* __restrict__ A, int lda,
            const __half* __restrict__ W, int ldb,
            const float* __restrict__ bias,
            __half* __restrict__ qn, __half* __restrict__ kn,
            __half* __restrict__ vt, float* __restrict__ col, int K) {
    constexpr int BM = 128, BN = 128, WM = 32, WN = 64, BK = PROJ_BK, PAD = PROJ_PAD, STG = PROJ_STG;
    constexpr int IM = 2, IN = 8;

    extern __shared__ __align__(16) char psm[];
    __half (*As)[BM][BK + PAD] = (__half(*)[BM][BK + PAD])psm;
    __half (*Bs)[BN][BK + PAD] = (__half(*)[BN][BK + PAD])(psm + STG * BM * (BK + PAD) * 2);

    const int tid = threadIdx.x;
    const int wid = tid >> 5, lane = tid & 31;
    const int g = lane >> 2, tg = lane & 3;
    const int sub = lane >> 3, lrow = lane & 7;
    const int wm = (wid >> 1) * WM, wn = (wid & 1) * WN;

    const __half* Ab = A + (long long)blockIdx.y * BM * lda;
    const __half* Bb = W + (long long)blockIdx.x * BN * ldb;

    const int ktiles = K / BK;
    float acc[IM][IN][4] = {};

    auto issue = [&](int t, int s) {
        int k0 = t * BK;
#pragma unroll
        for (int c = 0; c < 4; c++) {
            int idx = tid + c * 256;
            int row = idx >> 3, cq = idx & 7;
            cpasync16(&As[s][row][cq * 8], Ab + (long long)row * lda + k0 + cq * 8);
        }
#pragma unroll
        for (int c = 0; c < 4; c++) {
            int idx = tid + c * 256;
            int row = idx >> 3, cq = idx & 7;
            cpasync16(&Bs[s][row][cq * 8], Bb + (long long)row * ldb + k0 + cq * 8);
        }
    };

    issue(0, 0); cpcommit();
    if (ktiles > 1) issue(1, 1);
    cpcommit();
    cpwait1();
    __syncthreads();

    int rs = 0;
    for (int t = 0; t < ktiles; t++) {
#pragma unroll
        for (int kk = 0; kk < BK; kk += 16) {
            unsigned a[IM][4], b[IN][2];
#pragma unroll
            for (int im = 0; im < IM; im++)
                ldsm4(a[im], &As[rs][wm + im * 16 + (sub & 1) * 8 + lrow][kk + (sub >> 1) * 8]);
#pragma unroll
            for (int inp = 0; inp < IN / 2; inp++) {
                unsigned tr[4];
                ldsm4(tr, &Bs[rs][wn + inp * 16 + (sub >> 1) * 8 + lrow][kk + (sub & 1) * 8]);
                b[2 * inp][0] = tr[0]; b[2 * inp][1] = tr[1];
                b[2 * inp + 1][0] = tr[2]; b[2 * inp + 1][1] = tr[3];
            }
#pragma unroll
            for (int im = 0; im < IM; im++)
#pragma unroll
                for (int in_ = 0; in_ < IN; in_++)
                    mma16(acc[im][in_], a[im], b[in_]);
        }
        if (t + 2 < ktiles) issue(t + 2, (rs + 2) % STG);
        cpcommit();
        cpwait1();
        __syncthreads();
        rs = (rs + 1) % STG;
    }

    const int sec  = blockIdx.x / 6;                       // 0=Q, 1=K, 2=V
    const int m0   = blockIdx.y * BM;
    const int b    = m0 / L;
    const int l0   = m0 % L;

    if (blockIdx.x == 12 && tid < 128) col[b * L + l0 + tid] = 0.f;

#pragma unroll
    for (int im = 0; im < IM; im++)
#pragma unroll
        for (int in_ = 0; in_ < IN; in_++) {
            int cc = blockIdx.x * BN + wn + in_ * 8 + tg * 2;
            float b0 = bias[cc], b1 = bias[cc + 1];
            acc[im][in_][0] = lrelu(acc[im][in_][0] + b0);
            acc[im][in_][1] = lrelu(acc[im][in_][1] + b1);
            acc[im][in_][2] = lrelu(acc[im][in_][2] + b0);
            acc[im][in_][3] = lrelu(acc[im][in_][3] + b1);
        }

    if (sec < 2) {
        const int hloc = (blockIdx.x % 6) * 2 + (wn >> 6);
        const long long z = (long long)b * NH + hloc;
        __half* dst = (sec == 0) ? qn : kn;
#pragma unroll
        for (int im = 0; im < IM; im++) {
            float ss0 = 0.f, ss1 = 0.f;
#pragma unroll
            for (int in_ = 0; in_ < IN; in_++) {
                ss0 += acc[im][in_][0] * acc[im][in_][0] + acc[im][in_][1] * acc[im][in_][1];
                ss1 += acc[im][in_][2] * acc[im][in_][2] + acc[im][in_][3] * acc[im][in_][3];
            }
            ss0 += __shfl_xor_sync(0xffffffffu, ss0, 1);
            ss0 += __shfl_xor_sync(0xffffffffu, ss0, 2);
            ss1 += __shfl_xor_sync(0xffffffffu, ss1, 1);
            ss1 += __shfl_xor_sync(0xffffffffu, ss1, 2);
            float r0 = 1.f / fmaxf(sqrtf(ss0), 1e-8f);
            float r1 = 1.f / fmaxf(sqrtf(ss1), 1e-8f);
            int lA = l0 + wm + im * 16 + g;
            int lB = lA + 8;
#pragma unroll
            for (int in_ = 0; in_ < IN; in_++) {
                int dcol = in_ * 8 + tg * 2;
                *(__half2*)&dst[(z * L + lA) * HD + dcol] =
                    __floats2half2_rn(acc[im][in_][0] * r0, acc[im][in_][1] * r0);
                *(__half2*)&dst[(z * L + lB) * HD + dcol] =
                    __floats2half2_rn(acc[im][in_][2] * r1, acc[im][in_][3] * r1);
            }
        }
    } else {
        __half (*sv)[136] = (__half(*)[136])Bs;
#pragma unroll
        for (int p = 0; p < 2; p++) {
            __syncthreads();
            if ((wn >> 6) == p) {
#pragma unroll
                for (int im = 0; im < IM; im++)
#pragma unroll
                    for (int in_ = 0; in_ < IN; in_++) {
                        int d = in_ * 8 + tg * 2;
                        int l = wm + im * 16 + g;
                        sv[d][l]         = __float2half_rn(acc[im][in_][0]);
                        sv[d + 1][l]     = __float2half_rn(acc[im][in_][1]);
                        sv[d][l + 8]     = __float2half_rn(acc[im][in_][2]);
                        sv[d + 1][l + 8] = __float2half_rn(acc[im][in_][3]);
                    }
            }
            __syncthreads();
            long long z = (long long)b * NH + (blockIdx.x % 6) * 2 + p;
#pragma unroll
            for (int c = 0; c < 4; c++) {
                int idx = tid + c * 256;
                int d = idx >> 4, lc = (idx & 15) * 8;
                *(uint4*)(vt + (z * HD + d) * L + l0 + lc) = *(uint4*)&sv[d][lc];
            }
        }
    }
}

// ---------------- 3. fused scores + LN(heads): 2 heads/stage, ldmatrix, coalesced writes ----------------
#define ATTLN5_SMEM (4*64*72*2 + 4*32*72*2)   // 55296
__global__ void __launch_bounds__(256, 2)
attln5_k(const __half* __restrict__ kn, const __half* __restrict__ qn,
         __half* __restrict__ att, const float* __restrict__ gamma,
         const float* __restrict__ beta) {
    extern __shared__ __align__(16) char smraw[];
    __half (*kbuf)[64][72] = (__half(*)[64][72])smraw;
    __half (*qbuf)[32][72] = (__half(*)[32][72])(smraw + 4*64*72*2);
    __half (*tile)[40] = (__half(*)[40])smraw;   // aliases kbuf after compute

    const int tid = threadIdx.x;
    const int wid = tid >> 5, lane = tid & 31;
    const int g = lane >> 2, tg = lane & 3;
    const int sub = lane >> 3, lrow = lane & 7;
    const int wm = (wid >> 1) * 16, wn = (wid & 1) * 16;
    const int J0 = blockIdx.x * 32, I0 = blockIdx.y * 64, b = blockIdx.z;

    const __half* kb = kn + ((long long)b * NH * L + I0) * HD;
    const __half* qb = qn + ((long long)b * NH * L + J0) * HD;

    __half2 sc[NH][4];

#define ISSUE(h)                                                                  \
    {                                                                             \
        int s_ = (h) & 3;                                                         \
        long long hoff = (long long)(h) * L * HD;                                 \
        _Pragma("unroll")                                                         \
        for (int c = 0; c < 2; c++) {                                             \
            int idx = tid + c * 256;                                              \
            int r = idx >> 3, jc = idx & 7;                                       \
            cpasync16(&kbuf[s_][r][jc * 8], kb + hoff + (long long)r * HD + jc * 8); \
        }                                                                         \
        { int r = tid >> 3, jc = tid & 7;                                         \
          cpasync16(&qbuf[s_][r][jc * 8], qb + hoff + (long long)r * HD + jc * 8); } \
        cpcommit();                                                               \
    }

#define COMPUTE(h)                                                                \
    {                                                                             \
        int s_ = (h) & 3;                                                         \
        float acc[2][4] = {};                                                     \
        _Pragma("unroll")                                                         \
        for (int kk = 0; kk < 64; kk += 16) {                                     \
            unsigned a[4], bb[4];                                                 \
            ldsm4(a, &kbuf[s_][wm + (sub & 1) * 8 + lrow][kk + (sub >> 1) * 8]);  \
            ldsm4(bb, &qbuf[s_][wn + (sub >> 1) * 8 + lrow][kk + (sub & 1) * 8]); \
            mma16(acc[0], a, &bb[0]);                                             \
            mma16(acc[1], a, &bb[2]);                                             \
        }                                                                         \
        sc[h][0] = __floats2half2_rn(acc[0][0], acc[0][1]);                       \
        sc[h][1] = __floats2half2_rn(acc[0][2], acc[0][3]);                       \
        sc[h][2] = __floats2half2_rn(acc[1][0], acc[1][1]);                       \
        sc[h][3] = __floats2half2_rn(acc[1][2], acc[1][3]);                       \
    }

    ISSUE(0); ISSUE(1); ISSUE(2); ISSUE(3);
    cpwait2();
    __syncthreads();

#pragma unroll
    for (int p = 0; p < 6; p++) {
        COMPUTE(2 * p);
        COMPUTE(2 * p + 1);
        __syncthreads();
        if (p + 2 < 6) {
            ISSUE(2 * p + 4);
            ISSUE(2 * p + 5);
        } else {
            cpcommit(); cpcommit();
        }
        cpwait2();
        __syncthreads();
    }
#undef ISSUE
#undef COMPUTE

    // LN across heads, in registers (overwrite sc with LN'd values)
    float gm[NH], be[NH];
#pragma unroll
    for (int h = 0; h < NH; h++) { gm[h] = gamma[h]; be[h] = beta[h]; }
#pragma unroll
    for (int p = 0; p < 4; p++) {
        float mux = 0.f, muy = 0.f;
#pragma unroll
        for (int h = 0; h < NH; h++) {
            float2 f = __half22float2(sc[h][p]);
            mux += f.x; muy += f.y;
        }
        mux *= (1.f / NH); muy *= (1.f / NH);
        float varx = 0.f, vary = 0.f;
#pragma unroll
        for (int h = 0; h < NH; h++) {
            float2 f = __half22float2(sc[h][p]);
            float dx = f.x - mux, dy = f.y - muy;
            varx += dx * dx; vary += dy * dy;
        }
        float rsx = rsqrtf(varx * (1.f / NH) + 1e-5f);
        float rsy = rsqrtf(vary * (1.f / NH) + 1e-5f);
#pragma unroll
        for (int h = 0; h < NH; h++) {
            float2 f = __half22float2(sc[h][p]);
            sc[h][p] = __floats2half2_rn((f.x - mux) * rsx * gm[h] + be[h],
                                         (f.y - muy) * rsy * gm[h] + be[h]);
        }
    }

    // staged, coalesced output: per head stage 64x32 tile in smem, write 64B rows
    __half* ob = att + (long long)b * NH * LL + (long long)I0 * L + J0;
    const int trow = tid >> 2, tcol = (tid & 3) * 8;
#pragma unroll
    for (int h = 0; h < NH; h++) {
        __syncthreads();
#pragma unroll
        for (int p = 0; p < 4; p++) {
            int i = wm + g + ((p & 1) ? 8 : 0);
            int j = wn + ((p >> 1) ? 8 : 0) + tg * 2;
            *(__half2*)&tile[i][j] = sc[h][p];
        }
        __syncthreads();
        *(uint4*)&ob[(long long)h * LL + (long long)trow * L + tcol] =
            *(uint4*)&tile[trow][tcol];
    }
}

// ---------------- 4. fused softmax + colsum + att@V (ldmatrix, fp16 out) ----------------
#define SMATTV_SMEM (64*520*2 + 2*64*72*2)   // 84992
__global__ void __launch_bounds__(256)
smattv_k(const __half* __restrict__ att, const __half* __restrict__ vt,
         __half* __restrict__ out, float* __restrict__ col) {
    extern __shared__ __align__(16) char smem_raw[];
    __half (*satt)[520] = (__half(*)[520])smem_raw;
    __half (*vbuf)[64][72] = (__half(*)[64][72])(smem_raw + 64*520*2);

    const int tid = threadIdx.x;
    const int wid = tid >> 5, lane = tid & 31;
    const int g = lane >> 2, tg = lane & 3;
    const int sub = lane >> 3, lrow = lane & 7;
    const int wm = (wid >> 1) * 16, wn = (wid & 1) * 32;
    const int I0 = blockIdx.x * 64;
    const int z = blockIdx.y;
    const int b = z / NH, h = z % NH;

    const __half* abase = att + (long long)z * LL + (long long)I0 * L;
    const __half* vbase = vt + (long long)z * HD * L;

#pragma unroll
    for (int c = 0; c < 16; c++) {
        int idx = tid + c * 256;
        int r = idx >> 6, jc = idx & 63;
        cpasync16(&satt[r][jc * 8], abase + (long long)r * L + jc * 8);
    }
    cpcommit();

#define ISSUEV(kt, s)                                                            \
    {                                                                            \
        _Pragma("unroll")                                                        \
        for (int c = 0; c < 2; c++) {                                            \
            int idx = tid + c * 256;                                             \
            int r = idx >> 3, jc = idx & 7;                                      \
            cpasync16(&vbuf[s][r][jc * 8], vbase + (long long)r * L + (kt) * 64 + jc * 8); \
        }                                                                        \
    }
    ISSUEV(0, 0); cpcommit();
    cpwait1();
    __syncthreads();

    for (int k = 0; k < 8; k++) {
        int r = wid * 8 + k;
        float v[16];
        float m = -1e30f;
#pragma unroll
        for (int q = 0; q < 8; q++) {
            float2 f = __half22float2(*(__half2*)&satt[r][lane * 2 + q * 64]);
            v[2 * q] = f.x; v[2 * q + 1] = f.y;
            m = fmaxf(m, fmaxf(f.x, f.y));
        }
#pragma unroll
        for (int o = 16; o; o >>= 1) m = fmaxf(m, __shfl_xor_sync(0xffffffffu, m, o));
        float s = 0.f;
#pragma unroll
        for (int q = 0; q < 16; q++) { v[q] = __expf(v[q] - m); s += v[q]; }
#pragma unroll
        for (int o = 16; o; o >>= 1) s += __shfl_xor_sync(0xffffffffu, s, o);
        float inv = 1.f / s;
#pragma unroll
        for (int q = 0; q < 8; q++)
            *(__half2*)&satt[r][lane * 2 + q * 64] =
                __floats2half2_rn(v[2 * q] * inv, v[2 * q + 1] * inv);
    }
    __syncthreads();

    {
        int j = tid * 2;
        float c0 = 0.f, c1 = 0.f;
#pragma unroll 8
        for (int r = 0; r < 64; r++) {
            float2 f = __half22float2(*(__half2*)&satt[r][j]);
            c0 += f.x; c1 += f.y;
        }
        atomicAdd(&col[b * L + j], c0 * (1.f / NH));
        atomicAdd(&col[b * L + j + 1], c1 * (1.f / NH));
    }

    float acc[4][4] = {};
    int rs = 0;
    for (int kt = 0; kt < 8; kt++) {
        if (kt + 1 < 8) ISSUEV(kt + 1, rs ^ 1);
        cpcommit();
        cpwait1();
        __syncthreads();
#pragma unroll
        for (int kk = 0; kk < 64; kk += 16) {
            unsigned a[4], b0[4], b1[4];
            ldsm4(a, &satt[wm + (sub & 1) * 8 + lrow][kt * 64 + kk + (sub >> 1) * 8]);
            ldsm4(b0, &vbuf[rs][wn + (sub >> 1) * 8 + lrow][kk + (sub & 1) * 8]);
            ldsm4(b1, &vbuf[rs][wn + 16 + (sub >> 1) * 8 + lrow][kk + (sub & 1) * 8]);
            mma16(acc[0], a, &b0[0]);
            mma16(acc[1], a, &b0[2]);
            mma16(acc[2], a, &b1[0]);
            mma16(acc[3], a, &b1[2]);
        }
        rs ^= 1;
        __syncthreads();
    }
#undef ISSUEV

    __half* ob = out + ((long long)b * L + I0) * D + h * HD;
#pragma unroll
    for (int in_ = 0; in_ < 4; in_++) {
        int c = wn + in_ * 8 + tg * 2;
        *(__half2*)&ob[(long long)(wm + g) * D + c] =
            __floats2half2_rn(acc[in_][0], acc[in_][1]);
        *(__half2*)&ob[(long long)(wm + g + 8) * D + c] =
            __floats2half2_rn(acc[in_][2], acc[in_][3]);
    }
}

// ---------------- 5. per-token class probs (fp16 activations AND weights) ----------------
__global__ void probs_k(const __half* __restrict__ out, const __half* __restrict__ Wout,
                        const float* __restrict__ bout, float* __restrict__ probs) {
    int bl = blockIdx.x;
    int warp = threadIdx.x >> 5, lane = threadIdx.x & 31;
    __shared__ float s[NC];
    __shared__ float mx, sum;
    const __half* row = out + (long long)bl * D;
#pragma unroll
    for (int cc = 0; cc < 4; cc++) {
        int c = warp * 4 + cc;
        const __half* w = Wout + c * D;
        float acc = 0.f;
        for (int k = lane * 2; k < D; k += 64) {
            float2 f = __half22float2(*(const __half2*)(row + k));
            float2 ww = __half22float2(*(const __half2*)(w + k));
            acc += f.x * ww.x + f.y * ww.y;
        }
#pragma unroll
        for (int o = 16; o; o >>= 1) acc += __shfl_down_sync(0xffffffffu, acc, o);
        if (lane == 0) s[c] = acc + bout[c];
    }
    __syncthreads();
    if (threadIdx.x == 0) {
        float m = -1e30f;
        for (int c = 0; c < NC; c++) m = fmaxf(m, s[c]);
        float ss = 0.f;
        for (int c = 0; c < NC; c++) ss += __expf(s[c] - m);
        mx = m; sum = ss;
    }
    __syncthreads();
    if (threadIdx.x < NC)
        probs[(long long)bl * NC + threadIdx.x] = __expf(s[threadIdx.x] - mx) / sum;
}

// ---------------- 6. fused token weights softmax + final reduce ----------------
__global__ void __launch_bounds__(512)
wfinal_k(const int* __restrict__ ids, const float* __restrict__ col,
         const float* __restrict__ probs, float* __restrict__ dout, int first) {
    int b = blockIdx.x, l = threadIdx.x;
    int wid = l >> 5, lane = l & 31;
    __shared__ float red[512];
    __shared__ float psum[16][NC];

    float w = (ids[b * L + l] != 0 ? 1.f : 0.f) * col[b * L + l];
    red[l] = w;
    __syncthreads();
    for (int o = 256; o; o >>= 1) { if (l < o) red[l] = fmaxf(red[l], red[l + o]); __syncthreads(); }
    float mxv = red[0];
    __syncthreads();
    float e = __expf(w - mxv);
    red[l] = e;
    __syncthreads();
    for (int o = 256; o; o >>= 1) { if (l < o) red[l] += red[l + o]; __syncthreads(); }
    float wg = e / red[0];

    const float* pb = probs + (long long)(b * L + l) * NC;
    float myp[NC];
#pragma unroll
    for (int c = 0; c < NC; c++) myp[c] = wg * pb[c];
#pragma unroll
    for (int c = 0; c < NC; c++) {
        float v = myp[c];
#pragma unroll
        for (int o = 16; o; o >>= 1) v += __shfl_xor_sync(0xffffffffu, v, o);
        if (lane == 0) psum[wid][c] = v;
    }
    __syncthreads();
    if (l < NC) {
        float s = 0.f;
#pragma unroll
        for (int q = 0; q < 16; q++) s += psum[q][l];
        float v = 0.5f * s;
        dout[b * NC + l] = first ? v : dout[b * NC + l] + v;
    }
}

// ---------------- launch ----------------
extern "C" void kernel_launch(void* const* d_in, const int* in_sizes, int n_in,
                              void* d_out, int out_size) {
    (void)in_sizes; (void)n_in; (void)out_size;
    const int*   ids   = (const int*)d_in[0];
    const float* wv    = (const float*)d_in[1];
    const float* emb   = (const float*)d_in[2];
    const float* W_t   = (const float*)d_in[3];
    const float* b_t   = (const float*)d_in[4];
    const float* gam_t = (const float*)d_in[5];
    const float* bet_t = (const float*)d_in[6];
    const float* Wo_t  = (const float*)d_in[7];
    const float* bo_t  = (const float*)d_in[8];
    const float* W_h   = (const float*)d_in[9];
    const float* b_h   = (const float*)d_in[10];
    const float* gam_h = (const float*)d_in[11];
    const float* bet_h = (const float*)d_in[12];
    const float* Wo_h  = (const float*)d_in[13];
    const float* bo_h  = (const float*)d_in[14];
    float* out = (float*)d_out;

    __half *px, *pwt, *pwh, *pwv, *pwot, *pwoh, *patt16, *pqn, *pkn, *pvt, *pout;
    __half *patt16_2, *pqn2, *pkn2, *pvt2, *pout2;
    float *pprobs, *pcol, *pprobs2, *pcol2;
    cudaGetSymbolAddress((void**)&px, g_x);
    cudaGetSymbolAddress((void**)&pwt, g_wt16);
    cudaGetSymbolAddress((void**)&pwh, g_wh16);
    cudaGetSymbolAddress((void**)&pwv, g_wv16);
    cudaGetSymbolAddress((void**)&pwot, g_wot16);
    cudaGetSymbolAddress((void**)&pwoh, g_woh16);
    cudaGetSymbolAddress((void**)&patt16, g_att16);
    cudaGetSymbolAddress((void**)&pqn, g_qn);
    cudaGetSymbolAddress((void**)&pkn, g_kn);
    cudaGetSymbolAddress((void**)&pvt, g_vt);
    cudaGetSymbolAddress((void**)&pout, g_out);
    cudaGetSymbolAddress((void**)&pprobs, g_probs);
    cudaGetSymbolAddress((void**)&pcol, g_col);
    cudaGetSymbolAddress((void**)&patt16_2, g_att16_2);
    cudaGetSymbolAddress((void**)&pqn2, g_qn2);
    cudaGetSymbolAddress((void**)&pkn2, g_kn2);
    cudaGetSymbolAddress((void**)&pvt2, g_vt2);
    cudaGetSymbolAddress((void**)&pout2, g_out2);
    cudaGetSymbolAddress((void**)&pprobs2, g_probs2);
    cudaGetSymbolAddress((void**)&pcol2, g_col2);

    cudaFuncSetAttribute(smattv_k, cudaFuncAttributeMaxDynamicSharedMemorySize, SMATTV_SMEM);
    cudaFuncSetAttribute(attln5_k, cudaFuncAttributeMaxDynamicSharedMemorySize, ATTLN5_SMEM);
    cudaFuncSetAttribute(projsplit_k, cudaFuncAttributeMaxDynamicSharedMemorySize, PROJ_SMEM);

    dim3 proj_grid(D3 / 128, BL / 128);
    dim3 attln_grid(L / 32, L / 64, Bsz);
    dim3 smattv_grid(L / 64, BH);

    // Fork a second stream for the independent hidden branch (graph-capturable;
    // created per call, intentionally not destroyed — see R7 notes).
    cudaStream_t s2;
    cudaStreamCreateWithFlags(&s2, cudaStreamNonBlocking);
    cudaEvent_t evFork, evJoin;
    cudaEventCreateWithFlags(&evFork, cudaEventDisableTiming);
    cudaEventCreateWithFlags(&evJoin, cudaEventDisableTiming);

    cudaEventRecord(evFork, 0);
    cudaStreamWaitEvent(s2, evFork, 0);

    // ===== token branch (main stream) =====
    embed_leaky_k<<<BL, 192>>>(ids, emb, px);
    convpad_k<<<D3, 192>>>(W_t, pwt, D, D);
    convpad_k<<<NC, 192>>>(Wo_t, pwot, D, D);
    projsplit_k<<<proj_grid, 256, PROJ_SMEM>>>(px, D, pwt, D, b_t, pqn, pkn, pvt, pcol, D);
    attln5_k<<<attln_grid, 256, ATTLN5_SMEM>>>(pkn, pqn, patt16, gam_t, bet_t);
    smattv_k<<<smattv_grid, 256, SMATTV_SMEM>>>(patt16, pvt, pout, pcol);
    probs_k<<<BL, 160>>>(pout, pwot, bo_t, pprobs);
    wfinal_k<<<Bsz, 512>>>(ids, pcol, pprobs, out, 1);

    // ===== hidden / word-vector branch (stream s2) =====
    convpad_k<<<D3, 128, 0, s2>>>(W_h, pwh, 300, KH);
    convpad_k<<<BL, 128, 0, s2>>>(wv, pwv, 300, KH);
    convpad_k<<<NC, 128, 0, s2>>>(Wo_h, pwoh, D, D);
    projsplit_k<<<proj_grid, 256, PROJ_SMEM, s2>>>(pwv, KH, pwh, KH, b_h, pqn2, pkn2, pvt2, pcol2, KH);
    attln5_k<<<attln_grid, 256, ATTLN5_SMEM, s2>>>(pkn2, pqn2, patt16_2, gam_h, bet_h);
    smattv_k<<<smattv_grid, 256, SMATTV_SMEM, s2>>>(patt16_2, pvt2, pout2, pcol2);
    probs_k<<<BL, 160, 0, s2>>>(pout2, pwoh, bo_h, pprobs2);

    // join: hidden-branch results folded into d_out on the main stream
    cudaEventRecord(evJoin, s2);
    cudaStreamWaitEvent(0, evJoin, 0);
    wfinal_k<<<Bsz, 512>>>(ids, pcol2, pprobs2, out, 0);
}